// round 14
// baseline (speedup 1.0000x reference)
#include <cuda_runtime.h>
#include <cuda_bf16.h>
#include <cstdint>

#define BB  16
#define SS  168
#define NN  200
#define HH  128
#define TT  24
#define NHH 4
#define DHH 32
#define NROWS (BB * NN * TT)   // 76800

#define AGG_SMEM (NN * HH * 4)

// ---- k_attn v4 smem map (u32/float units) ----
#define QT_P   68
#define A_QTH  0
#define A_QTL  6528
#define A_ESJH 13056
#define A_ESJL 24480
#define EJ_P   88          // 352B rows: 16B-aligned for ldmatrix, conflict-free
#define A_EJSH 13056
#define A_EJSL 24320       // 13056 + 128*88
#define SC_P   180
#define A_SC   36096
#define ATT_P  92
#define AP_P   260
#define A_APH  13056
#define A_APL  21376
#define BS_P   36
#define ATTN_FLOATS 53376
#define ATTN_SMEM_BYTES (ATTN_FLOATS * 4)   // 213504

// k_gates smem layout (unsigned units, pitch 68)
#define GA_PITCH 68
#define G_AH  0
#define G_AL  (G_AH + 64 * GA_PITCH)
#define G_BH  (G_AL + 64 * GA_PITCH)
#define G_BL  (G_BH + 128 * GA_PITCH)
#define G_DS  (G_BL + 128 * GA_PITCH)
#define G_SMEM_BYTES ((G_DS + 64 * 33) * 4)   // 112896

// ---------------- device scratch ----------------
__device__ float g_W2[HH * 640];
__device__ float g_bqk[512];
__device__ float g_hfold[(size_t)BB * NN * 640];
__device__ float g_sfold[TT * 640];
__device__ float g_agg[2][BB * NN * HH];
__device__ float g_aggWh[2][BB * NN * 4 * HH];   // PERMUTED cols: p = hh*4 + gate
__device__ float g_comb[(size_t)NROWS * HH];
__device__ float g_x1[(size_t)NROWS * HH];
__device__ float g_x2[(size_t)NROWS * HH];
__device__ unsigned g_lnx_hi[(size_t)NROWS * 64];
__device__ unsigned g_lnx_lo[(size_t)NROWS * 64];
__device__ __nv_bfloat16 g_WxT_hi[2][512 * 128];
__device__ __nv_bfloat16 g_WxT_lo[2][512 * 128];
__device__ float g_WoC[HH * HH];
__device__ float g_cvec[HH];
__device__ unsigned g_MTp_hi[128 * 256];
__device__ unsigned g_MTp_lo[128 * 256];

__device__ __forceinline__ float sigf(float x) {
    return __fdividef(1.f, 1.f + __expf(fminf(-x, 80.f)));
}
__device__ __forceinline__ float tanhfast(float x) {
    float e = __expf(fminf(2.f * x, 80.f));
    return __fdividef(e - 1.f, e + 1.f);
}
__device__ __forceinline__ unsigned pack_bf(float lo, float hi) {
    unsigned r;
    asm("cvt.rn.bf16x2.f32 %0, %1, %2;" : "=r"(r) : "f"(hi), "f"(lo));
    return r;
}
__device__ __forceinline__ void split2(float a, float b, unsigned& h, unsigned& l) {
    h = pack_bf(a, b);
    __nv_bfloat162 hb = *(__nv_bfloat162*)&h;
    l = pack_bf(a - __bfloat162float(hb.x), b - __bfloat162float(hb.y));
}
__device__ __forceinline__ void mma16816(float* c, unsigned a0, unsigned a1,
                                         unsigned a2, unsigned a3,
                                         unsigned b0, unsigned b1) {
    asm volatile(
        "mma.sync.aligned.m16n8k16.row.col.f32.bf16.bf16.f32 "
        "{%0,%1,%2,%3}, {%4,%5,%6,%7}, {%8,%9}, {%0,%1,%2,%3};"
        : "+f"(c[0]), "+f"(c[1]), "+f"(c[2]), "+f"(c[3])
        : "r"(a0), "r"(a1), "r"(a2), "r"(a3), "r"(b0), "r"(b1));
}
__device__ __forceinline__ unsigned smem_addr32(const void* p) {
    unsigned a;
    asm("{ .reg .u64 t; cvta.to.shared.u64 t, %1; cvt.u32.u64 %0, t; }" : "=r"(a) : "l"(p));
    return a;
}
__device__ __forceinline__ void ldm4(unsigned& r0, unsigned& r1, unsigned& r2,
                                     unsigned& r3, unsigned a) {
    asm volatile("ldmatrix.sync.aligned.m8n8.x4.shared.b16 {%0,%1,%2,%3}, [%4];"
                 : "=r"(r0), "=r"(r1), "=r"(r2), "=r"(r3) : "r"(a));
}
__device__ __forceinline__ void ldm2(unsigned& r0, unsigned& r1, unsigned a) {
    asm volatile("ldmatrix.sync.aligned.m8n8.x2.shared.b16 {%0,%1}, [%2];"
                 : "=r"(r0), "=r"(r1) : "r"(a));
}

// ---------------- prep kernels ----------------
__global__ void k_w2(const float* __restrict__ Wq, const float* __restrict__ Wk,
                     const float* __restrict__ ctxW, const float* __restrict__ bq) {
    int idx = blockIdx.x * 256 + threadIdx.x;
    int i = idx / 640, col = idx % 640;
    if (i < HH) {
        float acc;
        if (col < 512) {
            int h = col >> 7, j = col & 127;
            acc = 0.f;
            #pragma unroll 8
            for (int d = 0; d < 32; d++)
                acc += Wq[i * HH + h * 32 + d] * Wk[j * HH + h * 32 + d];
        } else {
            acc = ctxW[i * HH + (col - 512)];
        }
        g_W2[i * 640 + col] = acc;
    }
    if (idx < 512) {
        int h = idx >> 7, j = idx & 127;
        float a = 0.f;
        #pragma unroll 8
        for (int d = 0; d < 32; d++)
            a += bq[h * 32 + d] * Wk[j * HH + h * 32 + d];
        g_bqk[idx] = a;
    }
}

__global__ void k_wprep(const float* __restrict__ Wx0, const float* __restrict__ Wx1) {
    int idx = blockIdx.x * 256 + threadIdx.x;
    if (idx >= 2 * 512 * 128) return;
    int l = idx / (512 * 128);
    int rem = idx % (512 * 128);
    int p = rem / 128, i = rem % 128;
    const float* Wx = l ? Wx1 : Wx0;
    float v = Wx[i * 512 + (p & 3) * 128 + (p >> 2)];
    __nv_bfloat16 hi = __float2bfloat16(v);
    float lo = v - __bfloat162float(hi);
    g_WxT_hi[l][p * 128 + i] = hi;
    g_WxT_lo[l][p * 128 + i] = __float2bfloat16(lo);
}

__global__ void k_woc(const float* __restrict__ Wo, const float* __restrict__ ctxW) {
    int idx = blockIdx.x * 256 + threadIdx.x;
    int i = idx >> 7, c = idx & 127;
    float acc = 0.f;
    #pragma unroll 4
    for (int m = 0; m < 128; m++)
        acc += Wo[i * 128 + m] * ctxW[(128 + m) * 128 + c];
    g_WoC[i * 128 + c] = acc;
}

__global__ void k_mbig(const float* __restrict__ Wv) {
    int idx = blockIdx.x * 256 + threadIdx.x;
    int c = idx >> 8, pr = idx & 255;
    int h = pr >> 6, j2 = pr & 63;
    float m0 = 0.f, m1 = 0.f;
    #pragma unroll 8
    for (int d = 0; d < 32; d++) {
        float wc = g_WoC[(h * 32 + d) * 128 + c];
        m0 += Wv[(2 * j2) * 128 + h * 32 + d] * wc;
        m1 += Wv[(2 * j2 + 1) * 128 + h * 32 + d] * wc;
    }
    unsigned hh_, ll_;
    split2(m0, m1, hh_, ll_);
    g_MTp_hi[idx] = hh_;
    g_MTp_lo[idx] = ll_;
}

__global__ void k_cvec(const float* __restrict__ ctxb, const float* __restrict__ bo,
                       const float* __restrict__ bv, const float* __restrict__ ctxW) {
    int c = threadIdx.x;
    float acc = ctxb[c];
    #pragma unroll 4
    for (int i = 0; i < 128; i++) acc += bo[i] * ctxW[(128 + i) * 128 + c];
    #pragma unroll 4
    for (int j = 0; j < 128; j++) acc += bv[j] * g_WoC[j * 128 + c];
    g_cvec[c] = acc;
}

__global__ __launch_bounds__(640, 1)
void k_fold(const float* __restrict__ h1, const float* __restrict__ stepq) {
    __shared__ float aS[8 * HH];
    int r0 = blockIdx.x * 8;
    bool isq = (r0 >= BB * NN);
    const float* src = isq ? (stepq + (r0 - BB * NN) * HH) : (h1 + (size_t)r0 * HH);
    for (int idx = threadIdx.x; idx < 8 * HH; idx += 640) aS[idx] = src[idx];
    __syncthreads();
    int c = threadIdx.x;
    float acc[8];
    float binit = (isq && c < 512) ? g_bqk[c] : 0.f;
    #pragma unroll
    for (int k = 0; k < 8; k++) acc[k] = binit;
    #pragma unroll 4
    for (int i = 0; i < HH; i++) {
        float w = g_W2[i * 640 + c];
        #pragma unroll
        for (int k = 0; k < 8; k++) acc[k] += aS[k * HH + i] * w;
    }
    float* dst = isq ? (g_sfold + (r0 - BB * NN) * 640) : (g_hfold + (size_t)r0 * 640);
    #pragma unroll
    for (int k = 0; k < 8; k++) dst[k * 640 + c] = acc[k];
}

__global__ __launch_bounds__(512, 1)
void k_agg(const float* __restrict__ h0, const float* __restrict__ h1,
           const float* __restrict__ adj) {
    extern __shared__ float hS[];
    int c5 = blockIdx.x / 32;
    int lb = blockIdx.x % 32;
    int l = lb >> 4, b = lb & 15;
    const float* hsrc = (l ? h1 : h0) + (size_t)b * NN * HH;
    for (int idx = threadIdx.x; idx < NN * HH; idx += 512) hS[idx] = hsrc[idx];
    __syncthreads();
    int hh = threadIdx.x & 127, g = threadIdx.x >> 7;
    const float4* adj4 = (const float4*)adj;
    int n0 = g * 50 + c5 * 10;
    float acc[10];
    #pragma unroll
    for (int k = 0; k < 10; k++) acc[k] = 0.f;
    for (int m4 = 0; m4 < 50; m4++) {
        float4 av[10];
        #pragma unroll
        for (int k = 0; k < 10; k++) av[k] = adj4[(n0 + k) * 50 + m4];
        #pragma unroll
        for (int u = 0; u < 4; u++) {
            float hv = hS[(m4 * 4 + u) * HH + hh];
            #pragma unroll
            for (int k = 0; k < 10; k++)
                acc[k] += ((const float*)&av[k])[u] * hv;
        }
    }
    #pragma unroll
    for (int k = 0; k < 10; k++)
        g_agg[l][((size_t)b * NN + n0 + k) * HH + hh] = acc[k];
}

__global__ __launch_bounds__(512, 1)
void k_aggWh(const float* __restrict__ Wh0, const float* __restrict__ bb0,
             const float* __restrict__ Wh1, const float* __restrict__ bb1) {
    extern __shared__ float aggS[];
    int ch = blockIdx.x >> 5;
    int lb = blockIdx.x & 31;
    int l = lb >> 4, b = lb & 15;
    const float* Wh   = l ? Wh1 : Wh0;
    const float* bias = l ? bb1 : bb0;
    const float* asrc = g_agg[l] + (size_t)b * NN * HH;
    for (int idx = threadIdx.x; idx < NN * HH; idx += 512) aggS[idx] = asrc[idx];
    __syncthreads();
    int c = threadIdx.x;
    int perm = (c & 127) * 4 + (c >> 7);
    float bsv = bias[c];
    const float4* a4 = (const float4*)aggS;
    float* dst = g_aggWh[l] + (size_t)b * NN * 4 * HH;
    int n0 = ch * 50;
    float acc[50];
    #pragma unroll
    for (int k = 0; k < 50; k++) acc[k] = bsv;
    for (int i4 = 0; i4 < 32; i4++) {
        float w0 = Wh[(i4 * 4 + 0) * 512 + c];
        float w1 = Wh[(i4 * 4 + 1) * 512 + c];
        float w2 = Wh[(i4 * 4 + 2) * 512 + c];
        float w3 = Wh[(i4 * 4 + 3) * 512 + c];
        #pragma unroll
        for (int k = 0; k < 50; k++) {
            float4 a = a4[(n0 + k) * 32 + i4];
            acc[k] += a.x * w0 + a.y * w1 + a.z * w2 + a.w * w3;
        }
    }
    #pragma unroll
    for (int k = 0; k < 50; k++) dst[(n0 + k) * 512 + perm] = acc[k];
}

// ---------------- attention megakernel v4 (ldmatrix everywhere) ----------------
__global__ __launch_bounds__(512, 1)
void k_attn(const float* __restrict__ enc, float* __restrict__ out_attn)
{
    extern __shared__ float sm[];
    unsigned* su = (unsigned*)sm;
    float* sc = sm + A_SC;

    const int tid = threadIdx.x;
    const int b = blockIdx.x / NN, n = blockIdx.x % NN;
    const int bn = b * NN + n;
    const int w = tid >> 5, lane = tid & 31;

    const unsigned sbase = smem_addr32(sm);
    const int arow8 = (lane & 7) + ((lane >> 3) & 1) * 8;   // A-frag row offset
    const int ksel  = ((lane >> 4) & 1) * 4;                // A-frag k-half (u32)
    const int brow  = lane & 7;                              // B-frag row
    const int bksel = ((lane >> 3) & 1) * 4;                 // B-frag k-half

    // ---- P0: e_sj bf16 h/l + qt bf16 h/l ----
    {
        const float4* e4 = (const float4*)enc;
        for (int idx = tid; idx < SS * 32; idx += 512) {
            int s = idx >> 5, j4 = idx & 31;
            float4 v = e4[((size_t)(b * SS + s) * NN + n) * 32 + j4];
            unsigned h0, l0, h1, l1;
            split2(v.x, v.y, h0, l0);
            split2(v.z, v.w, h1, l1);
            unsigned* dh = su + A_ESJH + s * QT_P + j4 * 2;
            unsigned* dl = su + A_ESJL + s * QT_P + j4 * 2;
            dh[0] = h0; dh[1] = h1;
            dl[0] = l0; dl[1] = l1;
        }
        const float4* sf4 = (const float4*)g_sfold;
        const float4* hf4 = (const float4*)(g_hfold + (size_t)bn * 640);
        for (int idx = tid; idx < 96 * 32; idx += 512) {
            int r = idx >> 5, j4 = idx & 31;
            int t = r >> 2;
            float4 sa = sf4[t * 160 + (r & 3) * 32 + j4];
            float4 hb = hf4[(r & 3) * 32 + j4];
            unsigned h0, l0, h1, l1;
            split2(sa.x + hb.x, sa.y + hb.y, h0, l0);
            split2(sa.z + hb.z, sa.w + hb.w, h1, l1);
            unsigned* dh = su + A_QTH + r * QT_P + j4 * 2;
            unsigned* dl = su + A_QTL + r * QT_P + j4 * 2;
            dh[0] = h0; dh[1] = h1;
            dl[0] = l0; dl[1] = l1;
        }
    }
    __syncthreads();

    // ---- P3: scores = qt @ e^T (HMMA via ldmatrix) ----
    {
        const float scale = 0.17677669529663687f;
        const int g = lane >> 2, tg = lane & 3;
        const int aoff = arow8 * QT_P + ksel;
        const int boff = brow * QT_P + bksel;
        for (int job = w; job < 126; job += 16) {
            int mt = job / 21, nt = job % 21;
            float acc[4] = {0.f, 0.f, 0.f, 0.f};
            unsigned abase = sbase + 4u * (A_QTH + mt * 16 * QT_P + aoff);
            unsigned bbase = sbase + 4u * (A_ESJH + nt * 8 * QT_P + boff);
            #pragma unroll
            for (int kt = 0; kt < 8; kt++) {
                unsigned a0h, a1h, a2h, a3h, a0l, a1l, a2l, a3l;
                unsigned b0h, b1h, b0l, b1l;
                ldm4(a0h, a1h, a2h, a3h, abase + 32u * kt);
                ldm4(a0l, a1l, a2l, a3l, abase + 4u * (A_QTL - A_QTH) + 32u * kt);
                ldm2(b0h, b1h, bbase + 32u * kt);
                ldm2(b0l, b1l, bbase + 4u * (A_ESJL - A_ESJH) + 32u * kt);
                mma16816(acc, a0h, a1h, a2h, a3h, b0h, b1h);
                mma16816(acc, a0h, a1h, a2h, a3h, b0l, b1l);
                mma16816(acc, a0l, a1l, a2l, a3l, b0h, b1h);
            }
            int row = mt * 16 + g, col = nt * 8 + 2 * tg;
            *(float2*)&sc[row * SC_P + col]       = make_float2(acc[0] * scale, acc[1] * scale);
            *(float2*)&sc[(row + 8) * SC_P + col] = make_float2(acc[2] * scale, acc[3] * scale);
        }
    }
    __syncthreads();

    // ---- load e_js bf16 h/l (pitch 88; zero pad sp 84..87) ----
    {
        const float* eb = enc + ((size_t)b * SS * NN + n) * HH;
        for (int idx = tid; idx < 128 * EJ_P; idx += 512) {
            int j = idx & 127, sp = idx >> 7;
            unsigned h, l;
            if (sp < 84) {
                float v0 = eb[(size_t)(2 * sp) * NN * HH + j];
                float v1 = eb[(size_t)(2 * sp + 1) * NN * HH + j];
                split2(v0, v1, h, l);
            } else { h = 0u; l = 0u; }
            su[A_EJSH + j * EJ_P + sp] = h;
            su[A_EJSL + j * EJ_P + sp] = l;
        }
    }

    // ---- P4: softmax -> global attn + smem bf16 pairs ----
    for (int k6 = 0; k6 < 6; k6++) {
        int r = k6 * 16 + w;
        float v[6];
        float mx = -1e30f;
        #pragma unroll
        for (int u = 0; u < 6; u++) {
            int s = lane + 32 * u;
            v[u] = (s < SS) ? sc[r * SC_P + s] : -1e30f;
            mx = fmaxf(mx, v[u]);
        }
        #pragma unroll
        for (int off = 16; off > 0; off >>= 1)
            mx = fmaxf(mx, __shfl_xor_sync(0xffffffffu, mx, off));
        float sum = 0.f;
        #pragma unroll
        for (int u = 0; u < 6; u++) {
            int s = lane + 32 * u;
            if (s < SS) { v[u] = __expf(v[u] - mx); sum += v[u]; }
        }
        #pragma unroll
        for (int off = 16; off > 0; off >>= 1)
            sum += __shfl_xor_sync(0xffffffffu, sum, off);
        float inv = __fdividef(1.f, sum);
        int t = r >> 2, h = r & 3;
        float* gout = out_attn + ((((size_t)b * TT + t) * NHH + h) * NN + n) * SS;
        #pragma unroll
        for (int u = 0; u < 6; u++) {
            int s = lane + 32 * u;
            if (s < SS) { v[u] *= inv; gout[s] = v[u]; }
            else v[u] = 0.f;
        }
        __syncthreads();
        #pragma unroll
        for (int u = 0; u < 6; u++) {
            float av = v[u];
            float bnx = __shfl_down_sync(0xffffffffu, av, 1);
            int s = lane + 32 * u;
            if (!(lane & 1)) {
                int p = s >> 1;
                if (p < 88) {
                    unsigned hh_, ll_;
                    split2(av, bnx, hh_, ll_);
                    su[r * ATT_P + p] = hh_;
                    su[A_SC + r * ATT_P + p] = ll_;
                }
            }
        }
    }
    __syncthreads();

    // ---- P5: ce = attn @ e (ldmatrix HMMA; accumulators in registers) ----
    float acc5[6][4];
    #pragma unroll
    for (int jj = 0; jj < 6; jj++)
        #pragma unroll
        for (int m = 0; m < 4; m++) acc5[jj][m] = 0.f;
    {
        const int aoff = arow8 * ATT_P + ksel;
        const int boff = brow * EJ_P + bksel;
        unsigned bbase = sbase + 4u * (A_EJSH + w * 8 * EJ_P + boff);
        #pragma unroll
        for (int jj = 0; jj < 6; jj++) {
            unsigned abase = sbase + 4u * (jj * 16 * ATT_P + aoff);
            #pragma unroll
            for (int kt = 0; kt < 11; kt++) {
                unsigned a0h, a1h, a2h, a3h, a0l, a1l, a2l, a3l;
                unsigned b0h, b1h, b0l, b1l;
                ldm4(a0h, a1h, a2h, a3h, abase + 32u * kt);
                ldm4(a0l, a1l, a2l, a3l, abase + 4u * A_SC + 32u * kt);
                ldm2(b0h, b1h, bbase + 32u * kt);
                ldm2(b0l, b1l, bbase + 4u * (A_EJSL - A_EJSH) + 32u * kt);
                mma16816(acc5[jj], a0h, a1h, a2h, a3h, b0h, b1h);
                mma16816(acc5[jj], a0h, a1h, a2h, a3h, b0l, b1l);
                mma16816(acc5[jj], a0l, a1l, a2l, a3l, b0h, b1h);
            }
        }
    }
    __syncthreads();   // e_js fully consumed

    // ---- write A' = ce bf16 pairs into dead e_js region ----
    {
        const int g = lane >> 2, tg = lane & 3;
        int j2 = w * 4 + tg;
        #pragma unroll
        for (int jj = 0; jj < 6; jj++) {
            int r0 = jj * 16 + g, r1 = r0 + 8;
            unsigned hh_, ll_;
            int p0 = (r0 & 3) * 64 + j2, t0 = r0 >> 2;
            split2(acc5[jj][0], acc5[jj][1], hh_, ll_);
            su[A_APH + t0 * AP_P + p0] = hh_;
            su[A_APL + t0 * AP_P + p0] = ll_;
            int p1 = (r1 & 3) * 64 + j2, t1 = r1 >> 2;
            split2(acc5[jj][2], acc5[jj][3], hh_, ll_);
            su[A_APH + t1 * AP_P + p1] = hh_;
            su[A_APL + t1 * AP_P + p1] = ll_;
        }
        for (int i = tid; i < 8 * 256; i += 512) {
            int rr = 24 + (i >> 8), p = i & 255;
            su[A_APH + rr * AP_P + p] = 0u;
            su[A_APL + rr * AP_P + p] = 0u;
        }
    }

    // ---- P6: comb = ce @ Mbig + folds + cvec (ldmatrix HMMA) ----
    float acc6[2][4];
    #pragma unroll
    for (int mt = 0; mt < 2; mt++)
        #pragma unroll
        for (int m = 0; m < 4; m++) acc6[mt][m] = 0.f;

    {
        const int aoff = arow8 * AP_P + ksel;
        const int boff = brow * BS_P + bksel;
        for (int ck = 0; ck < 8; ck++) {
            __syncthreads();
            for (int i = tid; i < 4096; i += 512) {
                int c = i >> 5, pr = i & 31;
                su[A_SC + c * BS_P + pr]        = g_MTp_hi[c * 256 + ck * 32 + pr];
                su[A_SC + 4608 + c * BS_P + pr] = g_MTp_lo[c * 256 + ck * 32 + pr];
            }
            __syncthreads();
            unsigned bbase = sbase + 4u * (A_SC + w * 8 * BS_P + boff);
            #pragma unroll
            for (int mt = 0; mt < 2; mt++) {
                unsigned abase = sbase + 4u * (A_APH + mt * 16 * AP_P + ck * 32 + aoff);
                #pragma unroll
                for (int kt = 0; kt < 4; kt++) {
                    unsigned a0h, a1h, a2h, a3h, a0l, a1l, a2l, a3l;
                    unsigned b0h, b1h, b0l, b1l;
                    ldm4(a0h, a1h, a2h, a3h, abase + 32u * kt);
                    ldm4(a0l, a1l, a2l, a3l, abase + 4u * (A_APL - A_APH) + 32u * kt);
                    ldm2(b0h, b1h, bbase + 32u * kt);
                    ldm2(b0l, b1l, bbase + 4u * 4608 + 32u * kt);
                    mma16816(acc6[mt], a0h, a1h, a2h, a3h, b0h, b1h);
                    mma16816(acc6[mt], a0h, a1h, a2h, a3h, b0l, b1l);
                    mma16816(acc6[mt], a0l, a1l, a2l, a3l, b0h, b1h);
                }
            }
        }
    }
    // write comb rows 0..23
    {
        const int g = lane >> 2, tg = lane & 3;
        int c0 = w * 8 + 2 * tg;
        float2 cv = *(const float2*)&g_cvec[c0];
        float2 hf = *(const float2*)&g_hfold[(size_t)bn * 640 + 512 + c0];
        #pragma unroll
        for (int mt = 0; mt < 2; mt++) {
            int t0 = mt * 16 + g;
            float2 sf0 = *(const float2*)&g_sfold[t0 * 640 + 512 + c0];
            *(float2*)&g_comb[((size_t)bn * TT + t0) * HH + c0] =
                make_float2(acc6[mt][0] + cv.x + hf.x + sf0.x,
                            acc6[mt][1] + cv.y + hf.y + sf0.y);
            int t1 = t0 + 8;
            if (t1 < TT) {
                float2 sf1 = *(const float2*)&g_sfold[t1 * 640 + 512 + c0];
                *(float2*)&g_comb[((size_t)bn * TT + t1) * HH + c0] =
                    make_float2(acc6[mt][2] + cv.x + hf.x + sf1.x,
                                acc6[mt][3] + cv.y + hf.y + sf1.y);
            }
        }
    }
}

// ---------------- LN -> bf16 hi/lo ----------------
__global__ __launch_bounds__(512, 1)
void k_ln(int which, const float* __restrict__ lg, const float* __restrict__ lb) {
    const float* src = which ? g_x1 : g_comb;
    int warp = threadIdx.x >> 5, lane = threadIdx.x & 31;
    int row0 = blockIdx.x * 128;
    for (int it = 0; it < 8; it++) {
        int row = row0 + warp + it * 16;
        float4 x = ((const float4*)(src + (size_t)row * HH))[lane];
        float s1 = x.x + x.y + x.z + x.w;
        #pragma unroll
        for (int off = 16; off > 0; off >>= 1) s1 += __shfl_xor_sync(0xffffffffu, s1, off);
        float mean = s1 * (1.f / HH);
        float dx = x.x - mean, dy = x.y - mean, dz = x.z - mean, dw = x.w - mean;
        float s2 = dx * dx + dy * dy + dz * dz + dw * dw;
        #pragma unroll
        for (int off = 16; off > 0; off >>= 1) s2 += __shfl_xor_sync(0xffffffffu, s2, off);
        float inv = rsqrtf(s2 * (1.f / HH) + 1e-5f);
        float4 gg = ((const float4*)lg)[lane];
        float4 bbv = ((const float4*)lb)[lane];
        float y0 = dx * inv * gg.x + bbv.x;
        float y1 = dy * inv * gg.y + bbv.y;
        float y2 = dz * inv * gg.z + bbv.z;
        float y3 = dw * inv * gg.w + bbv.w;
        size_t o = (size_t)row * 64 + lane * 2;
        unsigned h0, l0, h1, l1;
        split2(y0, y1, h0, l0);
        split2(y2, y3, h1, l1);
        g_lnx_hi[o] = h0; g_lnx_hi[o + 1] = h1;
        g_lnx_lo[o] = l0; g_lnx_lo[o + 1] = l1;
    }
}

// ---------------- HMMA gates GEMM + fused LSTM cell (ldmatrix) ----------------
__global__ __launch_bounds__(256, 2)
void k_gates(int layer, const float* __restrict__ cg) {
    extern __shared__ unsigned su[];
    unsigned* Ah = su + G_AH;
    unsigned* Al = su + G_AL;
    float*    Ds = (float*)(su + G_DS);

    const float* resid = layer ? g_x1 : nullptr;
    float* xout = layer ? g_x2 : g_x1;

    const int tid = threadIdx.x;
    const int row0 = blockIdx.x * 64;
    const int w = tid >> 5, lane = tid & 31;
    const int g = lane >> 2, tg = lane & 3;
    const int mt = w >> 1, nh = w & 1;
    const int qpar = tg & 1;

    const unsigned sbase = smem_addr32(su);
    const int arow8 = (lane & 7) + ((lane >> 3) & 1) * 8;
    const int ksel  = ((lane >> 4) & 1) * 4;
    // B x4 q-pair mapping: mat = lane>>3: q = mat>>1, khalf = mat&1, row = lane&7
    const int bq_  = (lane >> 4) & 1;
    const int bk_  = ((lane >> 3) & 1) * 4;
    const int brw_ = lane & 7;

    {
        const uint4* ah4 = (const uint4*)g_lnx_hi + (size_t)row0 * 16;
        const uint4* al4 = (const uint4*)g_lnx_lo + (size_t)row0 * 16;
        for (int i = tid; i < 64 * 16; i += 256) {
            int r = i >> 4, m = i & 15;
            *(uint4*)(Ah + r * GA_PITCH + m * 4) = ah4[r * 16 + m];
            *(uint4*)(Al + r * GA_PITCH + m * 4) = al4[r * 16 + m];
        }
    }
    const uint4* WH = (const uint4*)g_WxT_hi[layer];
    const uint4* WL = (const uint4*)g_WxT_lo[layer];

    for (int nc = 0; nc < 4; nc++) {
        __syncthreads();
        for (int i = tid; i < 128 * 16; i += 256) {
            int r = i >> 4, m = i & 15;
            *(uint4*)(su + G_BH + r * GA_PITCH + m * 4) = WH[(nc * 128 + r) * 16 + m];
            *(uint4*)(su + G_BL + r * GA_PITCH + m * 4) = WL[(nc * 128 + r) * 16 + m];
        }
        __syncthreads();

        float acc[8][4];
        #pragma unroll
        for (int q = 0; q < 8; q++)
            #pragma unroll
            for (int m = 0; m < 4; m++) acc[q][m] = 0.f;

        const unsigned aoffA = (unsigned)((mt * 16 + arow8) * GA_PITCH + ksel);
        #pragma unroll
        for (int kt = 0; kt < 8; kt++) {
            unsigned a0h, a1h, a2h, a3h, a0l, a1l, a2l, a3l;
            ldm4(a0h, a1h, a2h, a3h, sbase + 4u * (G_AH + aoffA) + 32u * kt);
            ldm4(a0l, a1l, a2l, a3l, sbase + 4u * (G_AL + aoffA) + 32u * kt);
            #pragma unroll
            for (int qp = 0; qp < 4; qp++) {
                // x4 loads B frags for q = 2qp (r0,r1) and q = 2qp+1 (r2,r3)
                unsigned boff = (unsigned)(((nh * 8 + qp * 2 + bq_) * 8 + brw_) * GA_PITCH + bk_);
                unsigned bh0, bh1, bh2, bh3, bl0, bl1, bl2, bl3;
                ldm4(bh0, bh1, bh2, bh3, sbase + 4u * (G_BH + boff) + 32u * kt);
                ldm4(bl0, bl1, bl2, bl3, sbase + 4u * (G_BL + boff) + 32u * kt);
                mma16816(acc[qp * 2],     a0h, a1h, a2h, a3h, bh0, bh1);
                mma16816(acc[qp * 2],     a0h, a1h, a2h, a3h, bl0, bl1);
                mma16816(acc[qp * 2],     a0l, a1l, a2l, a3l, bh0, bh1);
                mma16816(acc[qp * 2 + 1], a0h, a1h, a2h, a3h, bh2, bh3);
                mma16816(acc[qp * 2 + 1], a0h, a1h, a2h, a3h, bl2, bl3);
                mma16816(acc[qp * 2 + 1], a0l, a1l, a2l, a3l, bh2, bh3);
            }
        }

        #pragma unroll
        for (int q = 0; q < 8; q++) {
            float c0 = acc[q][0], c1 = acc[q][1], c2 = acc[q][2], c3 = acc[q][3];
            float r0 = __shfl_xor_sync(0xffffffffu, c0, 1);
            float r1 = __shfl_xor_sync(0xffffffffu, c1, 1);
            float r2 = __shfl_xor_sync(0xffffffffu, c2, 1);
            float r3 = __shfl_xor_sync(0xffffffffu, c3, 1);
            float gi = qpar ? r2 : c0;
            float gf = qpar ? r3 : c1;
            float gv = qpar ? c2 : r0;
            float go = qpar ? c3 : r1;
            int myrow = mt * 16 + g + 8 * qpar;
            int hhl = (nh * 8 + q) * 2 + (tg >> 1);
            int hh = nc * 32 + hhl;
            int grow = row0 + myrow;
            int bn = grow / TT;
            const float4 ag = *(const float4*)(g_aggWh[layer] + (size_t)bn * 512 + hh * 4);
            gi += ag.x; gf += ag.y; gv += ag.z; go += ag.w;
            float cv = cg[(size_t)bn * HH + hh];
            float cn = sigf(gf) * cv + sigf(gi) * tanhfast(gv);
            float hv = sigf(go) * tanhfast(cn);
            if (resid) hv += resid[(size_t)grow * HH + hh];
            Ds[myrow * 33 + hhl] = hv;
        }
        __syncthreads();

        for (int i = tid; i < 64 * 8; i += 256) {
            int r = i >> 3, m = i & 7;
            const float* d = Ds + r * 33 + m * 4;
            *(float4*)(xout + (size_t)(row0 + r) * HH + nc * 32 + m * 4) =
                make_float4(d[0], d[1], d[2], d[3]);
        }
    }
}

// ---------------- preds ----------------
__global__ __launch_bounds__(512, 1)
void k_preds(const float* __restrict__ outW, const float* __restrict__ outb,
             float* __restrict__ out_pred) {
    int warp = threadIdx.x >> 5, lane = threadIdx.x & 31;
    int row0 = blockIdx.x * 512;
    float4 w = ((const float4*)outW)[lane];
    float ob0 = outb[0];
    for (int it = 0; it < 32; it++) {
        int row = row0 + warp + it * 16;
        float4 x = ((const float4*)(g_x2 + (size_t)row * HH))[lane];
        float acc = x.x * w.x + x.y * w.y + x.z * w.z + x.w * w.w;
        #pragma unroll
        for (int off = 16; off > 0; off >>= 1)
            acc += __shfl_xor_sync(0xffffffffu, acc, off);
        if (lane == 0) {
            int bn = row / TT, t = row % TT;
            int b = bn / NN, n = bn % NN;
            out_pred[((size_t)b * TT + t) * NN + n] = acc + ob0;
        }
    }
}

extern "C" void kernel_launch(void* const* d_in, const int* in_sizes, int n_in,
                              void* d_out, int out_size) {
    const float* enc   = (const float*)d_in[0];
    const float* h0    = (const float*)d_in[1];
    const float* c0    = (const float*)d_in[2];
    const float* h1    = (const float*)d_in[3];
    const float* c1    = (const float*)d_in[4];
    const float* adj   = (const float*)d_in[5];
    const float* stepq = (const float*)d_in[6];
    const float* Wq    = (const float*)d_in[7];
    const float* bq    = (const float*)d_in[8];
    const float* Wk    = (const float*)d_in[9];
    // d_in[10] = bk: softmax-invariant, unused
    const float* Wv    = (const float*)d_in[11];
    const float* bv    = (const float*)d_in[12];
    const float* Wo    = (const float*)d_in[13];
    const float* bo    = (const float*)d_in[14];
    const float* ctxW  = (const float*)d_in[15];
    const float* ctxb  = (const float*)d_in[16];
    const float* Wx0   = (const float*)d_in[17];
    const float* Wh0   = (const float*)d_in[18];
    const float* b0    = (const float*)d_in[19];
    const float* lng0  = (const float*)d_in[20];
    const float* lnb0  = (const float*)d_in[21];
    const float* Wx1   = (const float*)d_in[22];
    const float* Wh1   = (const float*)d_in[23];
    const float* b1    = (const float*)d_in[24];
    const float* lng1  = (const float*)d_in[25];
    const float* lnb1  = (const float*)d_in[26];
    const float* outW  = (const float*)d_in[27];
    const float* outb  = (const float*)d_in[28];

    float* out      = (float*)d_out;
    float* out_pred = out;
    float* out_attn = out + (size_t)BB * TT * NN;

    cudaFuncSetAttribute(k_attn, cudaFuncAttributeMaxDynamicSharedMemorySize, ATTN_SMEM_BYTES);
    cudaFuncSetAttribute(k_agg, cudaFuncAttributeMaxDynamicSharedMemorySize, AGG_SMEM);
    cudaFuncSetAttribute(k_aggWh, cudaFuncAttributeMaxDynamicSharedMemorySize, AGG_SMEM);
    cudaFuncSetAttribute(k_gates, cudaFuncAttributeMaxDynamicSharedMemorySize, G_SMEM_BYTES);

    k_w2<<<320, 256>>>(Wq, Wk, ctxW, bq);
    k_wprep<<<512, 256>>>(Wx0, Wx1);
    k_woc<<<64, 256>>>(Wo, ctxW);
    k_mbig<<<128, 256>>>(Wv);
    k_cvec<<<1, 128>>>(ctxb, bo, bv, ctxW);
    k_fold<<<(BB * NN + TT) / 8, 640>>>(h1, stepq);
    k_agg<<<5 * 2 * BB, 512, AGG_SMEM>>>(h0, h1, adj);
    k_aggWh<<<4 * 2 * BB, 512, AGG_SMEM>>>(Wh0, b0, Wh1, b1);
    k_attn<<<BB * NN, 512, ATTN_SMEM_BYTES>>>(enc, out_attn);
    k_ln<<<NROWS / 128, 512>>>(0, lng0, lnb0);
    k_gates<<<NROWS / 64, 256, G_SMEM_BYTES>>>(0, c0);
    k_ln<<<NROWS / 128, 512>>>(1, lng1, lnb1);
    k_gates<<<NROWS / 64, 256, G_SMEM_BYTES>>>(1, c1);
    k_preds<<<NROWS / 512, 512>>>(outW, outb, out_pred);
}

// round 15
// speedup vs baseline: 1.0138x; 1.0138x over previous
#include <cuda_runtime.h>
#include <cuda_bf16.h>
#include <cstdint>

#define BB  16
#define SS  168
#define NN  200
#define HH  128
#define TT  24
#define NHH 4
#define DHH 32
#define NROWS (BB * NN * TT)   // 76800

#define AGG_SMEM  ((NN * HH + 40 * NN) * 4)   // 134400: h tile + 40 adj rows

// ---- k_attn smem map (u32/float units) ----
#define QT_P   68
#define A_QTH  0
#define A_QTL  6528
#define A_ESJH 13056
#define A_ESJL 24480
#define EJ_P   90
#define A_EJSH 13056
#define A_EJSL 24576
#define SC_P   180
#define A_SC   36096
#define ATT_P  92          // attn bf16 pairs: hi at [0,8832)
#define A_LO1  8832        // lo rows 0..44  (gap before e_js)
#define A_LO2  53376       // lo rows 45..95 (new tail space)
#define AP_P   260
#define A_APH  13056
#define A_APL  21376
#define BS_P   36
#define ATTN_FLOATS (A_LO2 + 51 * ATT_P)        // 58068
#define ATTN_SMEM_BYTES (ATTN_FLOATS * 4)       // 232272 (<= 232448)

// k_gates smem layout (unsigned units, pitch 68)
#define GA_PITCH 68
#define G_AH  0
#define G_AL  (G_AH + 64 * GA_PITCH)
#define G_BH  (G_AL + 64 * GA_PITCH)
#define G_BL  (G_BH + 128 * GA_PITCH)
#define G_DS  (G_BL + 128 * GA_PITCH)
#define G_SMEM_BYTES ((G_DS + 64 * 33) * 4)     // 112896

// ---------------- device scratch ----------------
__device__ float g_W2[HH * 640];
__device__ float g_bqk[512];
__device__ float g_hfold[(size_t)BB * NN * 640];
__device__ float g_sfold[TT * 640];
__device__ float g_agg[2][BB * NN * HH];
__device__ float g_aggWh[2][BB * NN * 4 * HH];   // PERMUTED cols: p = hh*4 + gate
__device__ float g_comb[(size_t)NROWS * HH];
__device__ float g_x1[(size_t)NROWS * HH];
__device__ float g_x2[(size_t)NROWS * HH];
__device__ unsigned g_lnx_hi[(size_t)NROWS * 64];
__device__ unsigned g_lnx_lo[(size_t)NROWS * 64];
__device__ __nv_bfloat16 g_WxT_hi[2][512 * 128];
__device__ __nv_bfloat16 g_WxT_lo[2][512 * 128];
__device__ float g_WoC[HH * HH];
__device__ float g_cvec[HH];
__device__ unsigned g_MTp_hi[128 * 256];
__device__ unsigned g_MTp_lo[128 * 256];

__device__ __forceinline__ float sigf(float x) {
    return __fdividef(1.f, 1.f + __expf(fminf(-x, 80.f)));
}
__device__ __forceinline__ float tanhfast(float x) {
    float e = __expf(fminf(2.f * x, 80.f));
    return __fdividef(e - 1.f, e + 1.f);
}
__device__ __forceinline__ unsigned pack_bf(float lo, float hi) {
    unsigned r;
    asm("cvt.rn.bf16x2.f32 %0, %1, %2;" : "=r"(r) : "f"(hi), "f"(lo));
    return r;
}
__device__ __forceinline__ void split2(float a, float b, unsigned& h, unsigned& l) {
    h = pack_bf(a, b);
    __nv_bfloat162 hb = *(__nv_bfloat162*)&h;
    l = pack_bf(a - __bfloat162float(hb.x), b - __bfloat162float(hb.y));
}
__device__ __forceinline__ void mma16816(float* c, unsigned a0, unsigned a1,
                                         unsigned a2, unsigned a3,
                                         unsigned b0, unsigned b1) {
    asm volatile(
        "mma.sync.aligned.m16n8k16.row.col.f32.bf16.bf16.f32 "
        "{%0,%1,%2,%3}, {%4,%5,%6,%7}, {%8,%9}, {%0,%1,%2,%3};"
        : "+f"(c[0]), "+f"(c[1]), "+f"(c[2]), "+f"(c[3])
        : "r"(a0), "r"(a1), "r"(a2), "r"(a3), "r"(b0), "r"(b1));
}
__device__ __forceinline__ int attlo(int r) {
    return (r < 45) ? (A_LO1 + r * ATT_P) : (A_LO2 + (r - 45) * ATT_P);
}

// ---------------- prep kernels ----------------
__global__ void k_w2(const float* __restrict__ Wq, const float* __restrict__ Wk,
                     const float* __restrict__ ctxW, const float* __restrict__ bq) {
    int idx = blockIdx.x * 256 + threadIdx.x;
    int i = idx / 640, col = idx % 640;
    if (i < HH) {
        float acc;
        if (col < 512) {
            int h = col >> 7, j = col & 127;
            acc = 0.f;
            #pragma unroll 8
            for (int d = 0; d < 32; d++)
                acc += Wq[i * HH + h * 32 + d] * Wk[j * HH + h * 32 + d];
        } else {
            acc = ctxW[i * HH + (col - 512)];
        }
        g_W2[i * 640 + col] = acc;
    }
    if (idx < 512) {
        int h = idx >> 7, j = idx & 127;
        float a = 0.f;
        #pragma unroll 8
        for (int d = 0; d < 32; d++)
            a += bq[h * 32 + d] * Wk[j * HH + h * 32 + d];
        g_bqk[idx] = a;
    }
}

__global__ void k_wprep(const float* __restrict__ Wx0, const float* __restrict__ Wx1) {
    int idx = blockIdx.x * 256 + threadIdx.x;
    if (idx >= 2 * 512 * 128) return;
    int l = idx / (512 * 128);
    int rem = idx % (512 * 128);
    int p = rem / 128, i = rem % 128;
    const float* Wx = l ? Wx1 : Wx0;
    float v = Wx[i * 512 + (p & 3) * 128 + (p >> 2)];
    __nv_bfloat16 hi = __float2bfloat16(v);
    float lo = v - __bfloat162float(hi);
    g_WxT_hi[l][p * 128 + i] = hi;
    g_WxT_lo[l][p * 128 + i] = __float2bfloat16(lo);
}

__global__ void k_woc(const float* __restrict__ Wo, const float* __restrict__ ctxW) {
    int idx = blockIdx.x * 256 + threadIdx.x;
    int i = idx >> 7, c = idx & 127;
    float acc = 0.f;
    #pragma unroll 4
    for (int m = 0; m < 128; m++)
        acc += Wo[i * 128 + m] * ctxW[(128 + m) * 128 + c];
    g_WoC[i * 128 + c] = acc;
}

__global__ void k_mbig(const float* __restrict__ Wv) {
    int idx = blockIdx.x * 256 + threadIdx.x;
    int c = idx >> 8, pr = idx & 255;
    int h = pr >> 6, j2 = pr & 63;
    float m0 = 0.f, m1 = 0.f;
    #pragma unroll 8
    for (int d = 0; d < 32; d++) {
        float wc = g_WoC[(h * 32 + d) * 128 + c];
        m0 += Wv[(2 * j2) * 128 + h * 32 + d] * wc;
        m1 += Wv[(2 * j2 + 1) * 128 + h * 32 + d] * wc;
    }
    unsigned hh_, ll_;
    split2(m0, m1, hh_, ll_);
    g_MTp_hi[idx] = hh_;
    g_MTp_lo[idx] = ll_;
}

__global__ void k_cvec(const float* __restrict__ ctxb, const float* __restrict__ bo,
                       const float* __restrict__ bv, const float* __restrict__ ctxW) {
    int c = threadIdx.x;
    float acc = ctxb[c];
    #pragma unroll 4
    for (int i = 0; i < 128; i++) acc += bo[i] * ctxW[(128 + i) * 128 + c];
    #pragma unroll 4
    for (int j = 0; j < 128; j++) acc += bv[j] * g_WoC[j * 128 + c];
    g_cvec[c] = acc;
}

__global__ __launch_bounds__(640, 1)
void k_fold(const float* __restrict__ h1, const float* __restrict__ stepq) {
    __shared__ float aS[8 * HH];
    int r0 = blockIdx.x * 8;
    bool isq = (r0 >= BB * NN);
    const float* src = isq ? (stepq + (r0 - BB * NN) * HH) : (h1 + (size_t)r0 * HH);
    for (int idx = threadIdx.x; idx < 8 * HH; idx += 640) aS[idx] = src[idx];
    __syncthreads();
    int c = threadIdx.x;
    float acc[8];
    float binit = (isq && c < 512) ? g_bqk[c] : 0.f;
    #pragma unroll
    for (int k = 0; k < 8; k++) acc[k] = binit;
    #pragma unroll 4
    for (int i = 0; i < HH; i++) {
        float w = g_W2[i * 640 + c];
        #pragma unroll
        for (int k = 0; k < 8; k++) acc[k] += aS[k * HH + i] * w;
    }
    float* dst = isq ? (g_sfold + (r0 - BB * NN) * 640) : (g_hfold + (size_t)r0 * 640);
    #pragma unroll
    for (int k = 0; k < 8; k++) dst[k * 640 + c] = acc[k];
}

// agg = adj @ h; adj rows staged in smem (broadcast LDS inner loop)
__global__ __launch_bounds__(512, 1)
void k_agg(const float* __restrict__ h0, const float* __restrict__ h1,
           const float* __restrict__ adj) {
    extern __shared__ float hS[];          // [200*128] h tile
    float* adjS = hS + NN * HH;            // [40*200] this block's adj rows
    int c5 = blockIdx.x / 32;
    int lb = blockIdx.x % 32;
    int l = lb >> 4, b = lb & 15;
    const float* hsrc = (l ? h1 : h0) + (size_t)b * NN * HH;
    for (int idx = threadIdx.x; idx < NN * HH; idx += 512) hS[idx] = hsrc[idx];
    for (int idx = threadIdx.x; idx < 40 * NN; idx += 512) {
        int r = idx / NN, m = idx % NN;    // r = g*10 + k
        int grow = (r / 10) * 50 + c5 * 10 + (r % 10);
        adjS[idx] = adj[grow * NN + m];
    }
    __syncthreads();
    int hh = threadIdx.x & 127, g = threadIdx.x >> 7;
    int n0 = g * 50 + c5 * 10;
    const float4* adjS4 = (const float4*)adjS;   // row pitch 50 float4
    float acc[10];
    #pragma unroll
    for (int k = 0; k < 10; k++) acc[k] = 0.f;
    for (int m4 = 0; m4 < 50; m4++) {
        float4 av[10];
        #pragma unroll
        for (int k = 0; k < 10; k++) av[k] = adjS4[(g * 10 + k) * 50 + m4];
        #pragma unroll
        for (int u = 0; u < 4; u++) {
            float hv = hS[(m4 * 4 + u) * HH + hh];
            #pragma unroll
            for (int k = 0; k < 10; k++)
                acc[k] += ((const float*)&av[k])[u] * hv;
        }
    }
    #pragma unroll
    for (int k = 0; k < 10; k++)
        g_agg[l][((size_t)b * NN + n0 + k) * HH + hh] = acc[k];
}

__global__ __launch_bounds__(512, 1)
void k_aggWh(const float* __restrict__ Wh0, const float* __restrict__ bb0,
             const float* __restrict__ Wh1, const float* __restrict__ bb1) {
    extern __shared__ float aggS[];
    int ch = blockIdx.x >> 5;
    int lb = blockIdx.x & 31;
    int l = lb >> 4, b = lb & 15;
    const float* Wh   = l ? Wh1 : Wh0;
    const float* bias = l ? bb1 : bb0;
    const float* asrc = g_agg[l] + (size_t)b * NN * HH;
    for (int idx = threadIdx.x; idx < NN * HH; idx += 512) aggS[idx] = asrc[idx];
    __syncthreads();
    int c = threadIdx.x;
    int perm = (c & 127) * 4 + (c >> 7);
    float bsv = bias[c];
    const float4* a4 = (const float4*)aggS;
    float* dst = g_aggWh[l] + (size_t)b * NN * 4 * HH;
    int n0 = ch * 50;
    float acc[50];
    #pragma unroll
    for (int k = 0; k < 50; k++) acc[k] = bsv;
    for (int i4 = 0; i4 < 32; i4++) {
        float w0 = Wh[(i4 * 4 + 0) * 512 + c];
        float w1 = Wh[(i4 * 4 + 1) * 512 + c];
        float w2 = Wh[(i4 * 4 + 2) * 512 + c];
        float w3 = Wh[(i4 * 4 + 3) * 512 + c];
        #pragma unroll
        for (int k = 0; k < 50; k++) {
            float4 a = a4[(n0 + k) * 32 + i4];
            acc[k] += a.x * w0 + a.y * w1 + a.z * w2 + a.w * w3;
        }
    }
    #pragma unroll
    for (int k = 0; k < 50; k++) dst[(n0 + k) * 512 + perm] = acc[k];
}

// ---------------- attention megakernel (R13 form + barrier-free softmax) ----------------
__global__ __launch_bounds__(512, 1)
void k_attn(const float* __restrict__ enc, float* __restrict__ out_attn)
{
    extern __shared__ float sm[];
    unsigned* su = (unsigned*)sm;
    float* sc = sm + A_SC;

    const int tid = threadIdx.x;
    const int b = blockIdx.x / NN, n = blockIdx.x % NN;
    const int bn = b * NN + n;
    const int w = tid >> 5, lane = tid & 31;
    const int g = lane >> 2, tg = lane & 3;

    // ---- P0: e_sj bf16 h/l + qt bf16 h/l ----
    {
        const float4* e4 = (const float4*)enc;
        for (int idx = tid; idx < SS * 32; idx += 512) {
            int s = idx >> 5, j4 = idx & 31;
            float4 v = e4[((size_t)(b * SS + s) * NN + n) * 32 + j4];
            unsigned h0, l0, h1, l1;
            split2(v.x, v.y, h0, l0);
            split2(v.z, v.w, h1, l1);
            unsigned* dh = su + A_ESJH + s * QT_P + j4 * 2;
            unsigned* dl = su + A_ESJL + s * QT_P + j4 * 2;
            dh[0] = h0; dh[1] = h1;
            dl[0] = l0; dl[1] = l1;
        }
        const float4* sf4 = (const float4*)g_sfold;
        const float4* hf4 = (const float4*)(g_hfold + (size_t)bn * 640);
        for (int idx = tid; idx < 96 * 32; idx += 512) {
            int r = idx >> 5, j4 = idx & 31;
            int t = r >> 2;
            float4 sa = sf4[t * 160 + (r & 3) * 32 + j4];
            float4 hb = hf4[(r & 3) * 32 + j4];
            unsigned h0, l0, h1, l1;
            split2(sa.x + hb.x, sa.y + hb.y, h0, l0);
            split2(sa.z + hb.z, sa.w + hb.w, h1, l1);
            unsigned* dh = su + A_QTH + r * QT_P + j4 * 2;
            unsigned* dl = su + A_QTL + r * QT_P + j4 * 2;
            dh[0] = h0; dh[1] = h1;
            dl[0] = l0; dl[1] = l1;
        }
    }
    __syncthreads();

    // ---- P3: scores = qt @ e^T (HMMA, manual frag loads) ----
    {
        const float scale = 0.17677669529663687f;
        for (int job = w; job < 126; job += 16) {
            int mt = job / 21, nt = job % 21;
            float acc[4] = {0.f, 0.f, 0.f, 0.f};
            int ra = (mt * 16 + g) * QT_P;
            int rb = (nt * 8 + g) * QT_P;
            #pragma unroll
            for (int kt = 0; kt < 8; kt++) {
                int ko = kt * 8 + tg;
                unsigned a0h = su[A_QTH + ra + ko];
                unsigned a1h = su[A_QTH + ra + 8 * QT_P + ko];
                unsigned a2h = su[A_QTH + ra + ko + 4];
                unsigned a3h = su[A_QTH + ra + 8 * QT_P + ko + 4];
                unsigned a0l = su[A_QTL + ra + ko];
                unsigned a1l = su[A_QTL + ra + 8 * QT_P + ko];
                unsigned a2l = su[A_QTL + ra + ko + 4];
                unsigned a3l = su[A_QTL + ra + 8 * QT_P + ko + 4];
                unsigned b0h = su[A_ESJH + rb + ko];
                unsigned b1h = su[A_ESJH + rb + ko + 4];
                unsigned b0l = su[A_ESJL + rb + ko];
                unsigned b1l = su[A_ESJL + rb + ko + 4];
                mma16816(acc, a0h, a1h, a2h, a3h, b0h, b1h);
                mma16816(acc, a0h, a1h, a2h, a3h, b0l, b1l);
                mma16816(acc, a0l, a1l, a2l, a3l, b0h, b1h);
            }
            int row = mt * 16 + g, col = nt * 8 + 2 * tg;
            *(float2*)&sc[row * SC_P + col]       = make_float2(acc[0] * scale, acc[1] * scale);
            *(float2*)&sc[(row + 8) * SC_P + col] = make_float2(acc[2] * scale, acc[3] * scale);
        }
    }
    __syncthreads();

    // ---- load e_js bf16 h/l (overwrites e_sj; qt region dead) ----
    {
        const float* eb = enc + ((size_t)b * SS * NN + n) * HH;
        for (int idx = tid; idx < 128 * EJ_P; idx += 512) {
            int j = idx & 127, sp = idx >> 7;
            unsigned h, l;
            if (sp < 84) {
                float v0 = eb[(size_t)(2 * sp) * NN * HH + j];
                float v1 = eb[(size_t)(2 * sp + 1) * NN * HH + j];
                split2(v0, v1, h, l);
            } else { h = 0u; l = 0u; }
            su[A_EJSH + j * EJ_P + sp] = h;
            su[A_EJSL + j * EJ_P + sp] = l;
        }
    }

    // ---- P4: softmax (fp32 exact) -> global attn + bf16 pairs (barrier-free) ----
    // hi -> su[r*92] (dead qt region); lo -> split chunks (no sc overlap)
    for (int k6 = 0; k6 < 6; k6++) {
        int r = k6 * 16 + w;
        float v[6];
        float mx = -1e30f;
        #pragma unroll
        for (int u = 0; u < 6; u++) {
            int s = lane + 32 * u;
            v[u] = (s < SS) ? sc[r * SC_P + s] : -1e30f;
            mx = fmaxf(mx, v[u]);
        }
        #pragma unroll
        for (int off = 16; off > 0; off >>= 1)
            mx = fmaxf(mx, __shfl_xor_sync(0xffffffffu, mx, off));
        float sum = 0.f;
        #pragma unroll
        for (int u = 0; u < 6; u++) {
            int s = lane + 32 * u;
            if (s < SS) { v[u] = __expf(v[u] - mx); sum += v[u]; }
        }
        #pragma unroll
        for (int off = 16; off > 0; off >>= 1)
            sum += __shfl_xor_sync(0xffffffffu, sum, off);
        float inv = __fdividef(1.f, sum);
        int t = r >> 2, h = r & 3;
        float* gout = out_attn + ((((size_t)b * TT + t) * NHH + h) * NN + n) * SS;
        #pragma unroll
        for (int u = 0; u < 6; u++) {
            int s = lane + 32 * u;
            if (s < SS) { v[u] *= inv; gout[s] = v[u]; }
            else v[u] = 0.f;
        }
        int lobase = attlo(r);
        #pragma unroll
        for (int u = 0; u < 6; u++) {
            float av = v[u];
            float bnx = __shfl_down_sync(0xffffffffu, av, 1);
            int s = lane + 32 * u;
            if (!(lane & 1)) {
                int p = s >> 1;
                if (p < 88) {
                    unsigned hh_, ll_;
                    split2(av, bnx, hh_, ll_);
                    su[r * ATT_P + p] = hh_;
                    su[lobase + p] = ll_;
                }
            }
        }
    }
    __syncthreads();

    // ---- P5: ce = attn @ e (HMMA; accumulators in registers) ----
    float acc5[6][4];
    #pragma unroll
    for (int jj = 0; jj < 6; jj++)
        #pragma unroll
        for (int m = 0; m < 4; m++) acc5[jj][m] = 0.f;
    {
        int rb = (w * 8 + g) * EJ_P;
        #pragma unroll
        for (int jj = 0; jj < 6; jj++) {
            int r0 = jj * 16 + g;
            int ra = r0 * ATT_P;
            int ral0 = attlo(r0), ral1 = attlo(r0 + 8);
            #pragma unroll
            for (int kt = 0; kt < 11; kt++) {
                int ko = kt * 8 + tg;
                unsigned a0h = su[ra + ko];
                unsigned a1h = su[ra + 8 * ATT_P + ko];
                unsigned a2h = su[ra + ko + 4];
                unsigned a3h = su[ra + 8 * ATT_P + ko + 4];
                unsigned a0l = su[ral0 + ko];
                unsigned a1l = su[ral1 + ko];
                unsigned a2l = su[ral0 + ko + 4];
                unsigned a3l = su[ral1 + ko + 4];
                unsigned b0h = su[A_EJSH + rb + ko];
                unsigned b1h = su[A_EJSH + rb + ko + 4];
                unsigned b0l = su[A_EJSL + rb + ko];
                unsigned b1l = su[A_EJSL + rb + ko + 4];
                mma16816(acc5[jj], a0h, a1h, a2h, a3h, b0h, b1h);
                mma16816(acc5[jj], a0h, a1h, a2h, a3h, b0l, b1l);
                mma16816(acc5[jj], a0l, a1l, a2l, a3l, b0h, b1h);
            }
        }
    }
    __syncthreads();   // e_js fully consumed

    // ---- write A' = ce bf16 pairs into dead e_js region ----
    {
        int j2 = w * 4 + tg;
        #pragma unroll
        for (int jj = 0; jj < 6; jj++) {
            int r0 = jj * 16 + g, r1 = r0 + 8;
            unsigned hh_, ll_;
            int p0 = (r0 & 3) * 64 + j2, t0 = r0 >> 2;
            split2(acc5[jj][0], acc5[jj][1], hh_, ll_);
            su[A_APH + t0 * AP_P + p0] = hh_;
            su[A_APL + t0 * AP_P + p0] = ll_;
            int p1 = (r1 & 3) * 64 + j2, t1 = r1 >> 2;
            split2(acc5[jj][2], acc5[jj][3], hh_, ll_);
            su[A_APH + t1 * AP_P + p1] = hh_;
            su[A_APL + t1 * AP_P + p1] = ll_;
        }
        for (int i = tid; i < 8 * 256; i += 512) {
            int rr = 24 + (i >> 8), p = i & 255;
            su[A_APH + rr * AP_P + p] = 0u;
            su[A_APL + rr * AP_P + p] = 0u;
        }
    }

    // ---- P6: comb = ce @ Mbig + folds + cvec (HMMA, 8 K-chunks) ----
    float acc6[2][4];
    #pragma unroll
    for (int mt = 0; mt < 2; mt++)
        #pragma unroll
        for (int m = 0; m < 4; m++) acc6[mt][m] = 0.f;

    for (int ck = 0; ck < 8; ck++) {
        __syncthreads();
        for (int i = tid; i < 4096; i += 512) {
            int c = i >> 5, pr = i & 31;
            su[A_SC + c * BS_P + pr]        = g_MTp_hi[c * 256 + ck * 32 + pr];
            su[A_SC + 4608 + c * BS_P + pr] = g_MTp_lo[c * 256 + ck * 32 + pr];
        }
        __syncthreads();
        int rb = (w * 8 + g) * BS_P;
        #pragma unroll
        for (int mt = 0; mt < 2; mt++) {
            int ra = (mt * 16 + g) * AP_P + ck * 32;
            #pragma unroll
            for (int kt = 0; kt < 4; kt++) {
                int ko = kt * 8 + tg;
                unsigned a0h = su[A_APH + ra + ko];
                unsigned a1h = su[A_APH + ra + 8 * AP_P + ko];
                unsigned a2h = su[A_APH + ra + ko + 4];
                unsigned a3h = su[A_APH + ra + 8 * AP_P + ko + 4];
                unsigned a0l = su[A_APL + ra + ko];
                unsigned a1l = su[A_APL + ra + 8 * AP_P + ko];
                unsigned a2l = su[A_APL + ra + ko + 4];
                unsigned a3l = su[A_APL + ra + 8 * AP_P + ko + 4];
                unsigned b0h = su[A_SC + rb + ko];
                unsigned b1h = su[A_SC + rb + ko + 4];
                unsigned b0l = su[A_SC + 4608 + rb + ko];
                unsigned b1l = su[A_SC + 4608 + rb + ko + 4];
                mma16816(acc6[mt], a0h, a1h, a2h, a3h, b0h, b1h);
                mma16816(acc6[mt], a0h, a1h, a2h, a3h, b0l, b1l);
                mma16816(acc6[mt], a0l, a1l, a2l, a3l, b0h, b1h);
            }
        }
    }
    // write comb rows 0..23
    {
        int c0 = w * 8 + 2 * tg;
        float2 cv = *(const float2*)&g_cvec[c0];
        float2 hf = *(const float2*)&g_hfold[(size_t)bn * 640 + 512 + c0];
        #pragma unroll
        for (int mt = 0; mt < 2; mt++) {
            int t0 = mt * 16 + g;
            float2 sf0 = *(const float2*)&g_sfold[t0 * 640 + 512 + c0];
            *(float2*)&g_comb[((size_t)bn * TT + t0) * HH + c0] =
                make_float2(acc6[mt][0] + cv.x + hf.x + sf0.x,
                            acc6[mt][1] + cv.y + hf.y + sf0.y);
            int t1 = t0 + 8;
            if (t1 < TT) {
                float2 sf1 = *(const float2*)&g_sfold[t1 * 640 + 512 + c0];
                *(float2*)&g_comb[((size_t)bn * TT + t1) * HH + c0] =
                    make_float2(acc6[mt][2] + cv.x + hf.x + sf1.x,
                                acc6[mt][3] + cv.y + hf.y + sf1.y);
            }
        }
    }
}

// ---------------- LN -> bf16 hi/lo ----------------
__global__ __launch_bounds__(512, 1)
void k_ln(int which, const float* __restrict__ lg, const float* __restrict__ lb) {
    const float* src = which ? g_x1 : g_comb;
    int warp = threadIdx.x >> 5, lane = threadIdx.x & 31;
    int row0 = blockIdx.x * 128;
    for (int it = 0; it < 8; it++) {
        int row = row0 + warp + it * 16;
        float4 x = ((const float4*)(src + (size_t)row * HH))[lane];
        float s1 = x.x + x.y + x.z + x.w;
        #pragma unroll
        for (int off = 16; off > 0; off >>= 1) s1 += __shfl_xor_sync(0xffffffffu, s1, off);
        float mean = s1 * (1.f / HH);
        float dx = x.x - mean, dy = x.y - mean, dz = x.z - mean, dw = x.w - mean;
        float s2 = dx * dx + dy * dy + dz * dz + dw * dw;
        #pragma unroll
        for (int off = 16; off > 0; off >>= 1) s2 += __shfl_xor_sync(0xffffffffu, s2, off);
        float inv = rsqrtf(s2 * (1.f / HH) + 1e-5f);
        float4 gg = ((const float4*)lg)[lane];
        float4 bbv = ((const float4*)lb)[lane];
        float y0 = dx * inv * gg.x + bbv.x;
        float y1 = dy * inv * gg.y + bbv.y;
        float y2 = dz * inv * gg.z + bbv.z;
        float y3 = dw * inv * gg.w + bbv.w;
        size_t o = (size_t)row * 64 + lane * 2;
        unsigned h0, l0, h1, l1;
        split2(y0, y1, h0, l0);
        split2(y2, y3, h1, l1);
        g_lnx_hi[o] = h0; g_lnx_hi[o + 1] = h1;
        g_lnx_lo[o] = l0; g_lnx_lo[o + 1] = l1;
    }
}

// ---------------- HMMA gates GEMM + fused LSTM cell (R13 form) ----------------
__global__ __launch_bounds__(256, 2)
void k_gates(int layer, const float* __restrict__ cg) {
    extern __shared__ unsigned su[];
    unsigned* Ah = su + G_AH;
    unsigned* Al = su + G_AL;
    unsigned* Bh = su + G_BH;
    unsigned* Bl = su + G_BL;
    float*    Ds = (float*)(su + G_DS);

    const float* resid = layer ? g_x1 : nullptr;
    float* xout = layer ? g_x2 : g_x1;

    const int tid = threadIdx.x;
    const int row0 = blockIdx.x * 64;
    const int w = tid >> 5, lane = tid & 31;
    const int g = lane >> 2, tg = lane & 3;
    const int mt = w >> 1, nh = w & 1;
    const int qpar = tg & 1;

    {
        const uint4* ah4 = (const uint4*)g_lnx_hi + (size_t)row0 * 16;
        const uint4* al4 = (const uint4*)g_lnx_lo + (size_t)row0 * 16;
        for (int i = tid; i < 64 * 16; i += 256) {
            int r = i >> 4, m = i & 15;
            *(uint4*)(Ah + r * GA_PITCH + m * 4) = ah4[r * 16 + m];
            *(uint4*)(Al + r * GA_PITCH + m * 4) = al4[r * 16 + m];
        }
    }
    const uint4* WH = (const uint4*)g_WxT_hi[layer];
    const uint4* WL = (const uint4*)g_WxT_lo[layer];

    for (int nc = 0; nc < 4; nc++) {
        __syncthreads();
        for (int i = tid; i < 128 * 16; i += 256) {
            int r = i >> 4, m = i & 15;
            *(uint4*)(Bh + r * GA_PITCH + m * 4) = WH[(nc * 128 + r) * 16 + m];
            *(uint4*)(Bl + r * GA_PITCH + m * 4) = WL[(nc * 128 + r) * 16 + m];
        }
        __syncthreads();

        float acc[8][4];
        #pragma unroll
        for (int q = 0; q < 8; q++)
            #pragma unroll
            for (int m = 0; m < 4; m++) acc[q][m] = 0.f;

        const int arow = mt * 16 + g;
        #pragma unroll
        for (int kt = 0; kt < 8; kt++) {
            const int ko = kt * 8 + tg;
            unsigned a0h = Ah[arow * GA_PITCH + ko];
            unsigned a1h = Ah[(arow + 8) * GA_PITCH + ko];
            unsigned a2h = Ah[arow * GA_PITCH + ko + 4];
            unsigned a3h = Ah[(arow + 8) * GA_PITCH + ko + 4];
            unsigned a0l = Al[arow * GA_PITCH + ko];
            unsigned a1l = Al[(arow + 8) * GA_PITCH + ko];
            unsigned a2l = Al[arow * GA_PITCH + ko + 4];
            unsigned a3l = Al[(arow + 8) * GA_PITCH + ko + 4];
            #pragma unroll
            for (int q = 0; q < 8; q++) {
                const int nrow = (nh * 8 + q) * 8 + g;
                unsigned b0h = Bh[nrow * GA_PITCH + ko];
                unsigned b1h = Bh[nrow * GA_PITCH + ko + 4];
                unsigned b0l = Bl[nrow * GA_PITCH + ko];
                unsigned b1l = Bl[nrow * GA_PITCH + ko + 4];
                mma16816(acc[q], a0h, a1h, a2h, a3h, b0h, b1h);
                mma16816(acc[q], a0h, a1h, a2h, a3h, b0l, b1l);
                mma16816(acc[q], a0l, a1l, a2l, a3l, b0h, b1h);
            }
        }

        #pragma unroll
        for (int q = 0; q < 8; q++) {
            float c0 = acc[q][0], c1 = acc[q][1], c2 = acc[q][2], c3 = acc[q][3];
            float r0 = __shfl_xor_sync(0xffffffffu, c0, 1);
            float r1 = __shfl_xor_sync(0xffffffffu, c1, 1);
            float r2 = __shfl_xor_sync(0xffffffffu, c2, 1);
            float r3 = __shfl_xor_sync(0xffffffffu, c3, 1);
            float gi = qpar ? r2 : c0;
            float gf = qpar ? r3 : c1;
            float gv = qpar ? c2 : r0;
            float go = qpar ? c3 : r1;
            int myrow = mt * 16 + g + 8 * qpar;
            int hhl = (nh * 8 + q) * 2 + (tg >> 1);
            int hh = nc * 32 + hhl;
            int grow = row0 + myrow;
            int bn = grow / TT;
            const float4 ag = *(const float4*)(g_aggWh[layer] + (size_t)bn * 512 + hh * 4);
            gi += ag.x; gf += ag.y; gv += ag.z; go += ag.w;
            float cv = cg[(size_t)bn * HH + hh];
            float cn = sigf(gf) * cv + sigf(gi) * tanhfast(gv);
            float hv = sigf(go) * tanhfast(cn);
            if (resid) hv += resid[(size_t)grow * HH + hh];
            Ds[myrow * 33 + hhl] = hv;
        }
        __syncthreads();

        for (int i = tid; i < 64 * 8; i += 256) {
            int r = i >> 3, m = i & 7;
            const float* d = Ds + r * 33 + m * 4;
            *(float4*)(xout + (size_t)(row0 + r) * HH + nc * 32 + m * 4) =
                make_float4(d[0], d[1], d[2], d[3]);
        }
    }
}

// ---------------- preds ----------------
__global__ __launch_bounds__(512, 1)
void k_preds(const float* __restrict__ outW, const float* __restrict__ outb,
             float* __restrict__ out_pred) {
    int warp = threadIdx.x >> 5, lane = threadIdx.x & 31;
    int row0 = blockIdx.x * 512;
    float4 w = ((const float4*)outW)[lane];
    float ob0 = outb[0];
    for (int it = 0; it < 32; it++) {
        int row = row0 + warp + it * 16;
        float4 x = ((const float4*)(g_x2 + (size_t)row * HH))[lane];
        float acc = x.x * w.x + x.y * w.y + x.z * w.z + x.w * w.w;
        #pragma unroll
        for (int off = 16; off > 0; off >>= 1)
            acc += __shfl_xor_sync(0xffffffffu, acc, off);
        if (lane == 0) {
            int bn = row / TT, t = row % TT;
            int b = bn / NN, n = bn % NN;
            out_pred[((size_t)b * TT + t) * NN + n] = acc + ob0;
        }
    }
}

extern "C" void kernel_launch(void* const* d_in, const int* in_sizes, int n_in,
                              void* d_out, int out_size) {
    const float* enc   = (const float*)d_in[0];
    const float* h0    = (const float*)d_in[1];
    const float* c0    = (const float*)d_in[2];
    const float* h1    = (const float*)d_in[3];
    const float* c1    = (const float*)d_in[4];
    const float* adj   = (const float*)d_in[5];
    const float* stepq = (const float*)d_in[6];
    const float* Wq    = (const float*)d_in[7];
    const float* bq    = (const float*)d_in[8];
    const float* Wk    = (const float*)d_in[9];
    // d_in[10] = bk: softmax-invariant, unused
    const float* Wv    = (const float*)d_in[11];
    const float* bv    = (const float*)d_in[12];
    const float* Wo    = (const float*)d_in[13];
    const float* bo    = (const float*)d_in[14];
    const float* ctxW  = (const float*)d_in[15];
    const float* ctxb  = (const float*)d_in[16];
    const float* Wx0   = (const float*)d_in[17];
    const float* Wh0   = (const float*)d_in[18];
    const float* b0    = (const float*)d_in[19];
    const float* lng0  = (const float*)d_in[20];
    const float* lnb0  = (const float*)d_in[21];
    const float* Wx1   = (const float*)d_in[22];
    const float* Wh1   = (const float*)d_in[23];
    const float* b1    = (const float*)d_in[24];
    const float* lng1  = (const float*)d_in[25];
    const float* lnb1  = (const float*)d_in[26];
    const float* outW  = (const float*)d_in[27];
    const float* outb  = (const float*)d_in[28];

    float* out      = (float*)d_out;
    float* out_pred = out;
    float* out_attn = out + (size_t)BB * TT * NN;

    cudaFuncSetAttribute(k_attn, cudaFuncAttributeMaxDynamicSharedMemorySize, ATTN_SMEM_BYTES);
    cudaFuncSetAttribute(k_agg, cudaFuncAttributeMaxDynamicSharedMemorySize, AGG_SMEM);
    cudaFuncSetAttribute(k_aggWh, cudaFuncAttributeMaxDynamicSharedMemorySize, NN * HH * 4);
    cudaFuncSetAttribute(k_gates, cudaFuncAttributeMaxDynamicSharedMemorySize, G_SMEM_BYTES);

    k_w2<<<320, 256>>>(Wq, Wk, ctxW, bq);
    k_wprep<<<512, 256>>>(Wx0, Wx1);
    k_woc<<<64, 256>>>(Wo, ctxW);
    k_mbig<<<128, 256>>>(Wv);
    k_cvec<<<1, 128>>>(ctxb, bo, bv, ctxW);
    k_fold<<<(BB * NN + TT) / 8, 640>>>(h1, stepq);
    k_agg<<<5 * 2 * BB, 512, AGG_SMEM>>>(h0, h1, adj);
    k_aggWh<<<4 * 2 * BB, 512, NN * HH * 4>>>(Wh0, b0, Wh1, b1);
    k_attn<<<BB * NN, 512, ATTN_SMEM_BYTES>>>(enc, out_attn);
    k_ln<<<NROWS / 128, 512>>>(0, lng0, lnb0);
    k_gates<<<NROWS / 64, 256, G_SMEM_BYTES>>>(0, c0);
    k_ln<<<NROWS / 128, 512>>>(1, lng1, lnb1);
    k_gates<<<NROWS / 64, 256, G_SMEM_BYTES>>>(1, c1);
    k_preds<<<NROWS / 512, 512>>>(outW, outb, out_pred);
}

// round 16
// speedup vs baseline: 1.0498x; 1.0355x over previous
#include <cuda_runtime.h>
#include <cuda_bf16.h>
#include <cstdint>

#define BB  16
#define SS  168
#define NN  200
#define HH  128
#define TT  24
#define NHH 4
#define DHH 32
#define NROWS (BB * NN * TT)   // 76800

#define AGG_SMEM  ((NN * HH + 40 * NN) * 4)   // 134400

// ---- k_attn smem map (u32/float units) ----
#define QT_P   68
#define A_QTH  0
#define A_QTL  6528
#define A_ESJH 13056
#define A_ESJL 24480
#define EJ_P   90
#define A_EJSH 13056
#define A_EJSL 24576
#define SC_P   180
#define A_SC   36096
#define ATT_P  92
#define A_LO1  8832
#define A_LO2  53376
#define AP_P   260
#define A_APH  13056
#define A_APL  21376
#define BS_P   36
#define ATTN_FLOATS (A_LO2 + 51 * ATT_P)        // 58068
#define ATTN_SMEM_BYTES (ATTN_FLOATS * 4)       // 232272

// k_gates smem layout (unsigned units, pitch 68)
#define GA_PITCH 68
#define G_AH  0
#define G_AL  (G_AH + 64 * GA_PITCH)
#define G_BH  (G_AL + 64 * GA_PITCH)
#define G_BL  (G_BH + 128 * GA_PITCH)
#define G_DS  (G_BL + 128 * GA_PITCH)
#define G_SMEM_BYTES ((G_DS + 64 * 33) * 4)     // 112896

// ---------------- device scratch ----------------
__device__ float g_W2[HH * 640];
__device__ float g_bqk[512];
__device__ float g_hfold[(size_t)BB * NN * 640];
__device__ float g_sfold[TT * 640];
__device__ float g_agg[2][BB * NN * HH];
__device__ float g_aggWh[2][BB * NN * 4 * HH];   // PERMUTED cols: p = hh*4 + gate
__device__ float g_comb[(size_t)NROWS * HH];
__device__ float g_x1[(size_t)NROWS * HH];
__device__ __nv_bfloat16 g_WxT_hi[2][512 * 128];
__device__ __nv_bfloat16 g_WxT_lo[2][512 * 128];
__device__ float g_WoC[HH * HH];
__device__ float g_cvec[HH];
__device__ unsigned g_MTp_hi[128 * 256];
__device__ unsigned g_MTp_lo[128 * 256];

__device__ __forceinline__ float sigf(float x) {
    return __fdividef(1.f, 1.f + __expf(fminf(-x, 80.f)));
}
__device__ __forceinline__ float tanhfast(float x) {
    float e = __expf(fminf(2.f * x, 80.f));
    return __fdividef(e - 1.f, e + 1.f);
}
__device__ __forceinline__ unsigned pack_bf(float lo, float hi) {
    unsigned r;
    asm("cvt.rn.bf16x2.f32 %0, %1, %2;" : "=r"(r) : "f"(hi), "f"(lo));
    return r;
}
__device__ __forceinline__ void split2(float a, float b, unsigned& h, unsigned& l) {
    h = pack_bf(a, b);
    __nv_bfloat162 hb = *(__nv_bfloat162*)&h;
    l = pack_bf(a - __bfloat162float(hb.x), b - __bfloat162float(hb.y));
}
__device__ __forceinline__ void mma16816(float* c, unsigned a0, unsigned a1,
                                         unsigned a2, unsigned a3,
                                         unsigned b0, unsigned b1) {
    asm volatile(
        "mma.sync.aligned.m16n8k16.row.col.f32.bf16.bf16.f32 "
        "{%0,%1,%2,%3}, {%4,%5,%6,%7}, {%8,%9}, {%0,%1,%2,%3};"
        : "+f"(c[0]), "+f"(c[1]), "+f"(c[2]), "+f"(c[3])
        : "r"(a0), "r"(a1), "r"(a2), "r"(a3), "r"(b0), "r"(b1));
}
__device__ __forceinline__ int attlo(int r) {
    return (r < 45) ? (A_LO1 + r * ATT_P) : (A_LO2 + (r - 45) * ATT_P);
}

// ---------------- fused prep A: w2 + woc + wprep ----------------
__global__ void k_prep_a(const float* __restrict__ Wq, const float* __restrict__ Wk,
                         const float* __restrict__ ctxW, const float* __restrict__ bq,
                         const float* __restrict__ Wo,
                         const float* __restrict__ Wx0, const float* __restrict__ Wx1) {
    int bid = blockIdx.x;
    if (bid < 320) {
        int idx = bid * 256 + threadIdx.x;
        int i = idx / 640, col = idx % 640;
        if (i < HH) {
            float acc;
            if (col < 512) {
                int h = col >> 7, j = col & 127;
                acc = 0.f;
                #pragma unroll 8
                for (int d = 0; d < 32; d++)
                    acc += Wq[i * HH + h * 32 + d] * Wk[j * HH + h * 32 + d];
            } else {
                acc = ctxW[i * HH + (col - 512)];
            }
            g_W2[i * 640 + col] = acc;
        }
        if (idx < 512) {
            int h = idx >> 7, j = idx & 127;
            float a = 0.f;
            #pragma unroll 8
            for (int d = 0; d < 32; d++)
                a += bq[h * 32 + d] * Wk[j * HH + h * 32 + d];
            g_bqk[idx] = a;
        }
    } else if (bid < 384) {
        int idx = (bid - 320) * 256 + threadIdx.x;   // 16384
        int i = idx >> 7, c = idx & 127;
        float acc = 0.f;
        #pragma unroll 4
        for (int m = 0; m < 128; m++)
            acc += Wo[i * 128 + m] * ctxW[(128 + m) * 128 + c];
        g_WoC[i * 128 + c] = acc;
    } else {
        int idx = (bid - 384) * 256 + threadIdx.x;   // 131072
        int l = idx / (512 * 128);
        int rem = idx % (512 * 128);
        int p = rem / 128, i = rem % 128;
        const float* Wx = l ? Wx1 : Wx0;
        float v = Wx[i * 512 + (p & 3) * 128 + (p >> 2)];
        __nv_bfloat16 hi = __float2bfloat16(v);
        float lo = v - __bfloat162float(hi);
        g_WxT_hi[l][p * 128 + i] = hi;
        g_WxT_lo[l][p * 128 + i] = __float2bfloat16(lo);
    }
}

// ---------------- fused prep B: mbig + cvec ----------------
__global__ void k_prep_b(const float* __restrict__ Wv, const float* __restrict__ ctxb,
                         const float* __restrict__ bo, const float* __restrict__ bv,
                         const float* __restrict__ ctxW) {
    int bid = blockIdx.x;
    if (bid < 128) {
        int idx = bid * 256 + threadIdx.x;
        int c = idx >> 8, pr = idx & 255;
        int h = pr >> 6, j2 = pr & 63;
        float m0 = 0.f, m1 = 0.f;
        #pragma unroll 8
        for (int d = 0; d < 32; d++) {
            float wc = g_WoC[(h * 32 + d) * 128 + c];
            m0 += Wv[(2 * j2) * 128 + h * 32 + d] * wc;
            m1 += Wv[(2 * j2 + 1) * 128 + h * 32 + d] * wc;
        }
        unsigned hh_, ll_;
        split2(m0, m1, hh_, ll_);
        g_MTp_hi[idx] = hh_;
        g_MTp_lo[idx] = ll_;
    } else if (threadIdx.x < 128) {
        int c = threadIdx.x;
        float acc = ctxb[c];
        #pragma unroll 4
        for (int i = 0; i < 128; i++) acc += bo[i] * ctxW[(128 + i) * 128 + c];
        #pragma unroll 4
        for (int j = 0; j < 128; j++) acc += bv[j] * g_WoC[j * 128 + c];
        g_cvec[c] = acc;
    }
}

__global__ __launch_bounds__(640, 1)
void k_fold(const float* __restrict__ h1, const float* __restrict__ stepq) {
    __shared__ float aS[8 * HH];
    int r0 = blockIdx.x * 8;
    bool isq = (r0 >= BB * NN);
    const float* src = isq ? (stepq + (r0 - BB * NN) * HH) : (h1 + (size_t)r0 * HH);
    for (int idx = threadIdx.x; idx < 8 * HH; idx += 640) aS[idx] = src[idx];
    __syncthreads();
    int c = threadIdx.x;
    float acc[8];
    float binit = (isq && c < 512) ? g_bqk[c] : 0.f;
    #pragma unroll
    for (int k = 0; k < 8; k++) acc[k] = binit;
    #pragma unroll 4
    for (int i = 0; i < HH; i++) {
        float w = g_W2[i * 640 + c];
        #pragma unroll
        for (int k = 0; k < 8; k++) acc[k] += aS[k * HH + i] * w;
    }
    float* dst = isq ? (g_sfold + (r0 - BB * NN) * 640) : (g_hfold + (size_t)r0 * 640);
    #pragma unroll
    for (int k = 0; k < 8; k++) dst[k * 640 + c] = acc[k];
}

__global__ __launch_bounds__(512, 1)
void k_agg(const float* __restrict__ h0, const float* __restrict__ h1,
           const float* __restrict__ adj) {
    extern __shared__ float hS[];
    float* adjS = hS + NN * HH;
    int c5 = blockIdx.x / 32;
    int lb = blockIdx.x % 32;
    int l = lb >> 4, b = lb & 15;
    const float* hsrc = (l ? h1 : h0) + (size_t)b * NN * HH;
    for (int idx = threadIdx.x; idx < NN * HH; idx += 512) hS[idx] = hsrc[idx];
    for (int idx = threadIdx.x; idx < 40 * NN; idx += 512) {
        int r = idx / NN, m = idx % NN;
        int grow = (r / 10) * 50 + c5 * 10 + (r % 10);
        adjS[idx] = adj[grow * NN + m];
    }
    __syncthreads();
    int hh = threadIdx.x & 127, g = threadIdx.x >> 7;
    int n0 = g * 50 + c5 * 10;
    const float4* adjS4 = (const float4*)adjS;
    float acc[10];
    #pragma unroll
    for (int k = 0; k < 10; k++) acc[k] = 0.f;
    for (int m4 = 0; m4 < 50; m4++) {
        float4 av[10];
        #pragma unroll
        for (int k = 0; k < 10; k++) av[k] = adjS4[(g * 10 + k) * 50 + m4];
        #pragma unroll
        for (int u = 0; u < 4; u++) {
            float hv = hS[(m4 * 4 + u) * HH + hh];
            #pragma unroll
            for (int k = 0; k < 10; k++)
                acc[k] += ((const float*)&av[k])[u] * hv;
        }
    }
    #pragma unroll
    for (int k = 0; k < 10; k++)
        g_agg[l][((size_t)b * NN + n0 + k) * HH + hh] = acc[k];
}

__global__ __launch_bounds__(512, 1)
void k_aggWh(const float* __restrict__ Wh0, const float* __restrict__ bb0,
             const float* __restrict__ Wh1, const float* __restrict__ bb1) {
    extern __shared__ float aggS[];
    int ch = blockIdx.x >> 5;
    int lb = blockIdx.x & 31;
    int l = lb >> 4, b = lb & 15;
    const float* Wh   = l ? Wh1 : Wh0;
    const float* bias = l ? bb1 : bb0;
    const float* asrc = g_agg[l] + (size_t)b * NN * HH;
    for (int idx = threadIdx.x; idx < NN * HH; idx += 512) aggS[idx] = asrc[idx];
    __syncthreads();
    int c = threadIdx.x;
    int perm = (c & 127) * 4 + (c >> 7);
    float bsv = bias[c];
    const float4* a4 = (const float4*)aggS;
    float* dst = g_aggWh[l] + (size_t)b * NN * 4 * HH;
    int n0 = ch * 50;
    float acc[50];
    #pragma unroll
    for (int k = 0; k < 50; k++) acc[k] = bsv;
    for (int i4 = 0; i4 < 32; i4++) {
        float w0 = Wh[(i4 * 4 + 0) * 512 + c];
        float w1 = Wh[(i4 * 4 + 1) * 512 + c];
        float w2 = Wh[(i4 * 4 + 2) * 512 + c];
        float w3 = Wh[(i4 * 4 + 3) * 512 + c];
        #pragma unroll
        for (int k = 0; k < 50; k++) {
            float4 a = a4[(n0 + k) * 32 + i4];
            acc[k] += a.x * w0 + a.y * w1 + a.z * w2 + a.w * w3;
        }
    }
    #pragma unroll
    for (int k = 0; k < 50; k++) dst[(n0 + k) * 512 + perm] = acc[k];
}

// ---------------- attention megakernel (unchanged from R15) ----------------
__global__ __launch_bounds__(512, 1)
void k_attn(const float* __restrict__ enc, float* __restrict__ out_attn)
{
    extern __shared__ float sm[];
    unsigned* su = (unsigned*)sm;
    float* sc = sm + A_SC;

    const int tid = threadIdx.x;
    const int b = blockIdx.x / NN, n = blockIdx.x % NN;
    const int bn = b * NN + n;
    const int w = tid >> 5, lane = tid & 31;
    const int g = lane >> 2, tg = lane & 3;

    {
        const float4* e4 = (const float4*)enc;
        for (int idx = tid; idx < SS * 32; idx += 512) {
            int s = idx >> 5, j4 = idx & 31;
            float4 v = e4[((size_t)(b * SS + s) * NN + n) * 32 + j4];
            unsigned h0, l0, h1, l1;
            split2(v.x, v.y, h0, l0);
            split2(v.z, v.w, h1, l1);
            unsigned* dh = su + A_ESJH + s * QT_P + j4 * 2;
            unsigned* dl = su + A_ESJL + s * QT_P + j4 * 2;
            dh[0] = h0; dh[1] = h1;
            dl[0] = l0; dl[1] = l1;
        }
        const float4* sf4 = (const float4*)g_sfold;
        const float4* hf4 = (const float4*)(g_hfold + (size_t)bn * 640);
        for (int idx = tid; idx < 96 * 32; idx += 512) {
            int r = idx >> 5, j4 = idx & 31;
            int t = r >> 2;
            float4 sa = sf4[t * 160 + (r & 3) * 32 + j4];
            float4 hb = hf4[(r & 3) * 32 + j4];
            unsigned h0, l0, h1, l1;
            split2(sa.x + hb.x, sa.y + hb.y, h0, l0);
            split2(sa.z + hb.z, sa.w + hb.w, h1, l1);
            unsigned* dh = su + A_QTH + r * QT_P + j4 * 2;
            unsigned* dl = su + A_QTL + r * QT_P + j4 * 2;
            dh[0] = h0; dh[1] = h1;
            dl[0] = l0; dl[1] = l1;
        }
    }
    __syncthreads();

    {
        const float scale = 0.17677669529663687f;
        for (int job = w; job < 126; job += 16) {
            int mt = job / 21, nt = job % 21;
            float acc[4] = {0.f, 0.f, 0.f, 0.f};
            int ra = (mt * 16 + g) * QT_P;
            int rb = (nt * 8 + g) * QT_P;
            #pragma unroll
            for (int kt = 0; kt < 8; kt++) {
                int ko = kt * 8 + tg;
                unsigned a0h = su[A_QTH + ra + ko];
                unsigned a1h = su[A_QTH + ra + 8 * QT_P + ko];
                unsigned a2h = su[A_QTH + ra + ko + 4];
                unsigned a3h = su[A_QTH + ra + 8 * QT_P + ko + 4];
                unsigned a0l = su[A_QTL + ra + ko];
                unsigned a1l = su[A_QTL + ra + 8 * QT_P + ko];
                unsigned a2l = su[A_QTL + ra + ko + 4];
                unsigned a3l = su[A_QTL + ra + 8 * QT_P + ko + 4];
                unsigned b0h = su[A_ESJH + rb + ko];
                unsigned b1h = su[A_ESJH + rb + ko + 4];
                unsigned b0l = su[A_ESJL + rb + ko];
                unsigned b1l = su[A_ESJL + rb + ko + 4];
                mma16816(acc, a0h, a1h, a2h, a3h, b0h, b1h);
                mma16816(acc, a0h, a1h, a2h, a3h, b0l, b1l);
                mma16816(acc, a0l, a1l, a2l, a3l, b0h, b1h);
            }
            int row = mt * 16 + g, col = nt * 8 + 2 * tg;
            *(float2*)&sc[row * SC_P + col]       = make_float2(acc[0] * scale, acc[1] * scale);
            *(float2*)&sc[(row + 8) * SC_P + col] = make_float2(acc[2] * scale, acc[3] * scale);
        }
    }
    __syncthreads();

    {
        const float* eb = enc + ((size_t)b * SS * NN + n) * HH;
        for (int idx = tid; idx < 128 * EJ_P; idx += 512) {
            int j = idx & 127, sp = idx >> 7;
            unsigned h, l;
            if (sp < 84) {
                float v0 = eb[(size_t)(2 * sp) * NN * HH + j];
                float v1 = eb[(size_t)(2 * sp + 1) * NN * HH + j];
                split2(v0, v1, h, l);
            } else { h = 0u; l = 0u; }
            su[A_EJSH + j * EJ_P + sp] = h;
            su[A_EJSL + j * EJ_P + sp] = l;
        }
    }

    for (int k6 = 0; k6 < 6; k6++) {
        int r = k6 * 16 + w;
        float v[6];
        float mx = -1e30f;
        #pragma unroll
        for (int u = 0; u < 6; u++) {
            int s = lane + 32 * u;
            v[u] = (s < SS) ? sc[r * SC_P + s] : -1e30f;
            mx = fmaxf(mx, v[u]);
        }
        #pragma unroll
        for (int off = 16; off > 0; off >>= 1)
            mx = fmaxf(mx, __shfl_xor_sync(0xffffffffu, mx, off));
        float sum = 0.f;
        #pragma unroll
        for (int u = 0; u < 6; u++) {
            int s = lane + 32 * u;
            if (s < SS) { v[u] = __expf(v[u] - mx); sum += v[u]; }
        }
        #pragma unroll
        for (int off = 16; off > 0; off >>= 1)
            sum += __shfl_xor_sync(0xffffffffu, sum, off);
        float inv = __fdividef(1.f, sum);
        int t = r >> 2, h = r & 3;
        float* gout = out_attn + ((((size_t)b * TT + t) * NHH + h) * NN + n) * SS;
        #pragma unroll
        for (int u = 0; u < 6; u++) {
            int s = lane + 32 * u;
            if (s < SS) { v[u] *= inv; gout[s] = v[u]; }
            else v[u] = 0.f;
        }
        int lobase = attlo(r);
        #pragma unroll
        for (int u = 0; u < 6; u++) {
            float av = v[u];
            float bnx = __shfl_down_sync(0xffffffffu, av, 1);
            int s = lane + 32 * u;
            if (!(lane & 1)) {
                int p = s >> 1;
                if (p < 88) {
                    unsigned hh_, ll_;
                    split2(av, bnx, hh_, ll_);
                    su[r * ATT_P + p] = hh_;
                    su[lobase + p] = ll_;
                }
            }
        }
    }
    __syncthreads();

    float acc5[6][4];
    #pragma unroll
    for (int jj = 0; jj < 6; jj++)
        #pragma unroll
        for (int m = 0; m < 4; m++) acc5[jj][m] = 0.f;
    {
        int rb = (w * 8 + g) * EJ_P;
        #pragma unroll
        for (int jj = 0; jj < 6; jj++) {
            int r0 = jj * 16 + g;
            int ra = r0 * ATT_P;
            int ral0 = attlo(r0), ral1 = attlo(r0 + 8);
            #pragma unroll
            for (int kt = 0; kt < 11; kt++) {
                int ko = kt * 8 + tg;
                unsigned a0h = su[ra + ko];
                unsigned a1h = su[ra + 8 * ATT_P + ko];
                unsigned a2h = su[ra + ko + 4];
                unsigned a3h = su[ra + 8 * ATT_P + ko + 4];
                unsigned a0l = su[ral0 + ko];
                unsigned a1l = su[ral1 + ko];
                unsigned a2l = su[ral0 + ko + 4];
                unsigned a3l = su[ral1 + ko + 4];
                unsigned b0h = su[A_EJSH + rb + ko];
                unsigned b1h = su[A_EJSH + rb + ko + 4];
                unsigned b0l = su[A_EJSL + rb + ko];
                unsigned b1l = su[A_EJSL + rb + ko + 4];
                mma16816(acc5[jj], a0h, a1h, a2h, a3h, b0h, b1h);
                mma16816(acc5[jj], a0h, a1h, a2h, a3h, b0l, b1l);
                mma16816(acc5[jj], a0l, a1l, a2l, a3l, b0h, b1h);
            }
        }
    }
    __syncthreads();

    {
        int j2 = w * 4 + tg;
        #pragma unroll
        for (int jj = 0; jj < 6; jj++) {
            int r0 = jj * 16 + g, r1 = r0 + 8;
            unsigned hh_, ll_;
            int p0 = (r0 & 3) * 64 + j2, t0 = r0 >> 2;
            split2(acc5[jj][0], acc5[jj][1], hh_, ll_);
            su[A_APH + t0 * AP_P + p0] = hh_;
            su[A_APL + t0 * AP_P + p0] = ll_;
            int p1 = (r1 & 3) * 64 + j2, t1 = r1 >> 2;
            split2(acc5[jj][2], acc5[jj][3], hh_, ll_);
            su[A_APH + t1 * AP_P + p1] = hh_;
            su[A_APL + t1 * AP_P + p1] = ll_;
        }
        for (int i = tid; i < 8 * 256; i += 512) {
            int rr = 24 + (i >> 8), p = i & 255;
            su[A_APH + rr * AP_P + p] = 0u;
            su[A_APL + rr * AP_P + p] = 0u;
        }
    }

    float acc6[2][4];
    #pragma unroll
    for (int mt = 0; mt < 2; mt++)
        #pragma unroll
        for (int m = 0; m < 4; m++) acc6[mt][m] = 0.f;

    for (int ck = 0; ck < 8; ck++) {
        __syncthreads();
        for (int i = tid; i < 4096; i += 512) {
            int c = i >> 5, pr = i & 31;
            su[A_SC + c * BS_P + pr]        = g_MTp_hi[c * 256 + ck * 32 + pr];
            su[A_SC + 4608 + c * BS_P + pr] = g_MTp_lo[c * 256 + ck * 32 + pr];
        }
        __syncthreads();
        int rb = (w * 8 + g) * BS_P;
        #pragma unroll
        for (int mt = 0; mt < 2; mt++) {
            int ra = (mt * 16 + g) * AP_P + ck * 32;
            #pragma unroll
            for (int kt = 0; kt < 4; kt++) {
                int ko = kt * 8 + tg;
                unsigned a0h = su[A_APH + ra + ko];
                unsigned a1h = su[A_APH + ra + 8 * AP_P + ko];
                unsigned a2h = su[A_APH + ra + ko + 4];
                unsigned a3h = su[A_APH + ra + 8 * AP_P + ko + 4];
                unsigned a0l = su[A_APL + ra + ko];
                unsigned a1l = su[A_APL + ra + 8 * AP_P + ko];
                unsigned a2l = su[A_APL + ra + ko + 4];
                unsigned a3l = su[A_APL + ra + 8 * AP_P + ko + 4];
                unsigned b0h = su[A_SC + rb + ko];
                unsigned b1h = su[A_SC + rb + ko + 4];
                unsigned b0l = su[A_SC + 4608 + rb + ko];
                unsigned b1l = su[A_SC + 4608 + rb + ko + 4];
                mma16816(acc6[mt], a0h, a1h, a2h, a3h, b0h, b1h);
                mma16816(acc6[mt], a0h, a1h, a2h, a3h, b0l, b1l);
                mma16816(acc6[mt], a0l, a1l, a2l, a3l, b0h, b1h);
            }
        }
    }
    {
        int c0 = w * 8 + 2 * tg;
        float2 cv = *(const float2*)&g_cvec[c0];
        float2 hf = *(const float2*)&g_hfold[(size_t)bn * 640 + 512 + c0];
        #pragma unroll
        for (int mt = 0; mt < 2; mt++) {
            int t0 = mt * 16 + g;
            float2 sf0 = *(const float2*)&g_sfold[t0 * 640 + 512 + c0];
            *(float2*)&g_comb[((size_t)bn * TT + t0) * HH + c0] =
                make_float2(acc6[mt][0] + cv.x + hf.x + sf0.x,
                            acc6[mt][1] + cv.y + hf.y + sf0.y);
            int t1 = t0 + 8;
            if (t1 < TT) {
                float2 sf1 = *(const float2*)&g_sfold[t1 * 640 + 512 + c0];
                *(float2*)&g_comb[((size_t)bn * TT + t1) * HH + c0] =
                    make_float2(acc6[mt][2] + cv.x + hf.x + sf1.x,
                                acc6[mt][3] + cv.y + hf.y + sf1.y);
            }
        }
    }
}

// ---------------- HMMA gates GEMM + fused LN + LSTM cell + preds ----------------
__global__ __launch_bounds__(256, 2)
void k_gates(int layer, const float* __restrict__ cg,
             const float* __restrict__ lg, const float* __restrict__ lb,
             const float* __restrict__ outW, const float* __restrict__ outb,
             float* __restrict__ out_pred) {
    extern __shared__ unsigned su[];
    unsigned* Ah = su + G_AH;
    unsigned* Al = su + G_AL;
    unsigned* Bh = su + G_BH;
    unsigned* Bl = su + G_BL;
    float*    Ds = (float*)(su + G_DS);
    float*    predS = Ds;   // layer-1 overlay (Ds unused when layer==1)

    const float* src   = layer ? g_x1 : g_comb;
    const float* resid = layer ? g_x1 : nullptr;
    float* xout = g_x1;     // only written for layer 0

    const int tid = threadIdx.x;
    const int row0 = blockIdx.x * 64;
    const int w = tid >> 5, lane = tid & 31;
    const int g = lane >> 2, tg = lane & 3;
    const int mt = w >> 1, nh = w & 1;
    const int qpar = tg & 1;

    if (layer && tid < 64) predS[tid] = 0.f;

    // ---- fused LN: 64 rows -> bf16 hi/lo in Ah/Al (identical math to k_ln) ----
    {
        float4 gg = ((const float4*)lg)[lane];
        float4 bbv = ((const float4*)lb)[lane];
        for (int it = 0; it < 8; it++) {
            int r = w + it * 8;
            float4 x = ((const float4*)(src + (size_t)(row0 + r) * HH))[lane];
            float s1 = x.x + x.y + x.z + x.w;
            #pragma unroll
            for (int off = 16; off > 0; off >>= 1) s1 += __shfl_xor_sync(0xffffffffu, s1, off);
            float mean = s1 * (1.f / HH);
            float dx = x.x - mean, dy = x.y - mean, dz = x.z - mean, dw = x.w - mean;
            float s2 = dx * dx + dy * dy + dz * dz + dw * dw;
            #pragma unroll
            for (int off = 16; off > 0; off >>= 1) s2 += __shfl_xor_sync(0xffffffffu, s2, off);
            float inv = rsqrtf(s2 * (1.f / HH) + 1e-5f);
            float y0 = dx * inv * gg.x + bbv.x;
            float y1 = dy * inv * gg.y + bbv.y;
            float y2 = dz * inv * gg.z + bbv.z;
            float y3 = dw * inv * gg.w + bbv.w;
            unsigned h0, l0, h1, l1;
            split2(y0, y1, h0, l0);
            split2(y2, y3, h1, l1);
            Ah[r * GA_PITCH + lane * 2]     = h0;
            Ah[r * GA_PITCH + lane * 2 + 1] = h1;
            Al[r * GA_PITCH + lane * 2]     = l0;
            Al[r * GA_PITCH + lane * 2 + 1] = l1;
        }
    }
    const uint4* WH = (const uint4*)g_WxT_hi[layer];
    const uint4* WL = (const uint4*)g_WxT_lo[layer];
    float predacc = 0.f;

    for (int nc = 0; nc < 4; nc++) {
        __syncthreads();
        for (int i = tid; i < 128 * 16; i += 256) {
            int r = i >> 4, m = i & 15;
            *(uint4*)(Bh + r * GA_PITCH + m * 4) = WH[(nc * 128 + r) * 16 + m];
            *(uint4*)(Bl + r * GA_PITCH + m * 4) = WL[(nc * 128 + r) * 16 + m];
        }
        __syncthreads();

        float acc[8][4];
        #pragma unroll
        for (int q = 0; q < 8; q++)
            #pragma unroll
            for (int m = 0; m < 4; m++) acc[q][m] = 0.f;

        const int arow = mt * 16 + g;
        #pragma unroll
        for (int kt = 0; kt < 8; kt++) {
            const int ko = kt * 8 + tg;
            unsigned a0h = Ah[arow * GA_PITCH + ko];
            unsigned a1h = Ah[(arow + 8) * GA_PITCH + ko];
            unsigned a2h = Ah[arow * GA_PITCH + ko + 4];
            unsigned a3h = Ah[(arow + 8) * GA_PITCH + ko + 4];
            unsigned a0l = Al[arow * GA_PITCH + ko];
            unsigned a1l = Al[(arow + 8) * GA_PITCH + ko];
            unsigned a2l = Al[arow * GA_PITCH + ko + 4];
            unsigned a3l = Al[(arow + 8) * GA_PITCH + ko + 4];
            #pragma unroll
            for (int q = 0; q < 8; q++) {
                const int nrow = (nh * 8 + q) * 8 + g;
                unsigned b0h = Bh[nrow * GA_PITCH + ko];
                unsigned b1h = Bh[nrow * GA_PITCH + ko + 4];
                unsigned b0l = Bl[nrow * GA_PITCH + ko];
                unsigned b1l = Bl[nrow * GA_PITCH + ko + 4];
                mma16816(acc[q], a0h, a1h, a2h, a3h, b0h, b1h);
                mma16816(acc[q], a0h, a1h, a2h, a3h, b0l, b1l);
                mma16816(acc[q], a0l, a1l, a2l, a3l, b0h, b1h);
            }
        }

        #pragma unroll
        for (int q = 0; q < 8; q++) {
            float c0 = acc[q][0], c1 = acc[q][1], c2 = acc[q][2], c3 = acc[q][3];
            float r0 = __shfl_xor_sync(0xffffffffu, c0, 1);
            float r1 = __shfl_xor_sync(0xffffffffu, c1, 1);
            float r2 = __shfl_xor_sync(0xffffffffu, c2, 1);
            float r3 = __shfl_xor_sync(0xffffffffu, c3, 1);
            float gi = qpar ? r2 : c0;
            float gf = qpar ? r3 : c1;
            float gv = qpar ? c2 : r0;
            float go = qpar ? c3 : r1;
            int myrow = mt * 16 + g + 8 * qpar;
            int hhl = (nh * 8 + q) * 2 + (tg >> 1);
            int hh = nc * 32 + hhl;
            int grow = row0 + myrow;
            int bn = grow / TT;
            const float4 ag = *(const float4*)(g_aggWh[layer] + (size_t)bn * 512 + hh * 4);
            gi += ag.x; gf += ag.y; gv += ag.z; go += ag.w;
            float cv = cg[(size_t)bn * HH + hh];
            float cn = sigf(gf) * cv + sigf(gi) * tanhfast(gv);
            float hv = sigf(go) * tanhfast(cn);
            if (layer) {
                hv += resid[(size_t)grow * HH + hh];
                predacc += hv * __ldg(&outW[hh]);
            } else {
                Ds[myrow * 33 + hhl] = hv;
            }
        }
        if (!layer) {
            __syncthreads();
            for (int i = tid; i < 64 * 8; i += 256) {
                int r = i >> 3, m = i & 7;
                const float* d = Ds + r * 33 + m * 4;
                *(float4*)(xout + (size_t)(row0 + r) * HH + nc * 32 + m * 4) =
                    make_float4(d[0], d[1], d[2], d[3]);
            }
        }
    }

    if (layer) {
        int myrow = mt * 16 + g + 8 * qpar;
        atomicAdd(&predS[myrow], predacc);
        __syncthreads();
        if (tid < 64) {
            int grow = row0 + tid;
            int bn = grow / TT, t = grow % TT;
            int b = bn / NN, n = bn % NN;
            out_pred[((size_t)b * TT + t) * NN + n] = predS[tid] + outb[0];
        }
    }
}

extern "C" void kernel_launch(void* const* d_in, const int* in_sizes, int n_in,
                              void* d_out, int out_size) {
    const float* enc   = (const float*)d_in[0];
    const float* h0    = (const float*)d_in[1];
    const float* c0    = (const float*)d_in[2];
    const float* h1    = (const float*)d_in[3];
    const float* c1    = (const float*)d_in[4];
    const float* adj   = (const float*)d_in[5];
    const float* stepq = (const float*)d_in[6];
    const float* Wq    = (const float*)d_in[7];
    const float* bq    = (const float*)d_in[8];
    const float* Wk    = (const float*)d_in[9];
    // d_in[10] = bk: softmax-invariant, unused
    const float* Wv    = (const float*)d_in[11];
    const float* bv    = (const float*)d_in[12];
    const float* Wo    = (const float*)d_in[13];
    const float* bo    = (const float*)d_in[14];
    const float* ctxW  = (const float*)d_in[15];
    const float* ctxb  = (const float*)d_in[16];
    const float* Wx0   = (const float*)d_in[17];
    const float* Wh0   = (const float*)d_in[18];
    const float* b0    = (const float*)d_in[19];
    const float* lng0  = (const float*)d_in[20];
    const float* lnb0  = (const float*)d_in[21];
    const float* Wx1   = (const float*)d_in[22];
    const float* Wh1   = (const float*)d_in[23];
    const float* b1    = (const float*)d_in[24];
    const float* lng1  = (const float*)d_in[25];
    const float* lnb1  = (const float*)d_in[26];
    const float* outW  = (const float*)d_in[27];
    const float* outb  = (const float*)d_in[28];

    float* out      = (float*)d_out;
    float* out_pred = out;
    float* out_attn = out + (size_t)BB * TT * NN;

    cudaFuncSetAttribute(k_attn, cudaFuncAttributeMaxDynamicSharedMemorySize, ATTN_SMEM_BYTES);
    cudaFuncSetAttribute(k_agg, cudaFuncAttributeMaxDynamicSharedMemorySize, AGG_SMEM);
    cudaFuncSetAttribute(k_aggWh, cudaFuncAttributeMaxDynamicSharedMemorySize, NN * HH * 4);
    cudaFuncSetAttribute(k_gates, cudaFuncAttributeMaxDynamicSharedMemorySize, G_SMEM_BYTES);

    k_prep_a<<<896, 256>>>(Wq, Wk, ctxW, bq, Wo, Wx0, Wx1);
    k_prep_b<<<129, 256>>>(Wv, ctxb, bo, bv, ctxW);
    k_fold<<<(BB * NN + TT) / 8, 640>>>(h1, stepq);
    k_agg<<<5 * 2 * BB, 512, AGG_SMEM>>>(h0, h1, adj);
    k_aggWh<<<4 * 2 * BB, 512, NN * HH * 4>>>(Wh0, b0, Wh1, b1);
    k_attn<<<BB * NN, 512, ATTN_SMEM_BYTES>>>(enc, out_attn);
    k_gates<<<NROWS / 64, 256, G_SMEM_BYTES>>>(0, c0, lng0, lnb0, outW, outb, out_pred);
    k_gates<<<NROWS / 64, 256, G_SMEM_BYTES>>>(1, c1, lng1, lnb1, outW, outb, out_pred);
}

// round 17
// speedup vs baseline: 1.0530x; 1.0030x over previous
#include <cuda_runtime.h>
#include <cuda_bf16.h>
#include <cstdint>

#define BB  16
#define SS  168
#define NN  200
#define TT  24
#define HH  128
#define NHH 4
#define NROWS (BB * NN * TT)   // 76800

#define AGG_SMEM  ((NN * HH + 40 * NN) * 4)   // 134400

// ---- k_attn smem map (u32/float units) ----
#define QT_P   68
#define A_QTH  0
#define A_QTL  6528
#define A_ESJH 13056
#define A_ESJL 24480
#define EJ_P   90
#define A_EJSH 13056
#define A_EJSL 24576
#define SC_P   180
#define A_SC   36096
#define ATT_P  92
#define A_LO1  8832
#define A_LO2  53376
#define AP_P   260
#define A_APH  13056
#define A_APL  21376
#define BS_P   36
#define ATTN_FLOATS (A_LO2 + 51 * ATT_P)        // 58068
#define ATTN_SMEM_BYTES (ATTN_FLOATS * 4)       // 232272

// k_gatesf smem layout (unsigned units, pitch 68)
#define GA_PITCH 68
#define G_AH  0
#define G_AL  (G_AH + 64 * GA_PITCH)
#define G_BH  (G_AL + 64 * GA_PITCH)
#define G_BL  (G_BH + 128 * GA_PITCH)
#define G_DS  (G_BL + 128 * GA_PITCH)
#define G_SMEM_BYTES ((G_DS + 64 * 33) * 4)     // 112896

// ---------------- device scratch ----------------
__device__ float g_W2[HH * 640];
__device__ float g_bqk[512];
__device__ float g_hfold[(size_t)BB * NN * 640];
__device__ float g_sfold[TT * 640];
__device__ float g_agg[2][BB * NN * HH];
__device__ float g_aggWh[2][BB * NN * 4 * HH];   // PERMUTED cols: p = hh*4 + gate
__device__ float g_comb[(size_t)NROWS * HH];
__device__ __nv_bfloat16 g_WxT_hi[2][512 * 128];
__device__ __nv_bfloat16 g_WxT_lo[2][512 * 128];
__device__ float g_WoC[HH * HH];
__device__ float g_cvec[HH];
__device__ unsigned g_MTp_hi[128 * 256];
__device__ unsigned g_MTp_lo[128 * 256];

__device__ __forceinline__ float sigf(float x) {
    return __fdividef(1.f, 1.f + __expf(fminf(-x, 80.f)));
}
__device__ __forceinline__ float tanhfast(float x) {
    float e = __expf(fminf(2.f * x, 80.f));
    return __fdividef(e - 1.f, e + 1.f);
}
__device__ __forceinline__ unsigned pack_bf(float lo, float hi) {
    unsigned r;
    asm("cvt.rn.bf16x2.f32 %0, %1, %2;" : "=r"(r) : "f"(hi), "f"(lo));
    return r;
}
__device__ __forceinline__ void split2(float a, float b, unsigned& h, unsigned& l) {
    h = pack_bf(a, b);
    __nv_bfloat162 hb = *(__nv_bfloat162*)&h;
    l = pack_bf(a - __bfloat162float(hb.x), b - __bfloat162float(hb.y));
}
__device__ __forceinline__ void mma16816(float* c, unsigned a0, unsigned a1,
                                         unsigned a2, unsigned a3,
                                         unsigned b0, unsigned b1) {
    asm volatile(
        "mma.sync.aligned.m16n8k16.row.col.f32.bf16.bf16.f32 "
        "{%0,%1,%2,%3}, {%4,%5,%6,%7}, {%8,%9}, {%0,%1,%2,%3};"
        : "+f"(c[0]), "+f"(c[1]), "+f"(c[2]), "+f"(c[3])
        : "r"(a0), "r"(a1), "r"(a2), "r"(a3), "r"(b0), "r"(b1));
}
__device__ __forceinline__ int attlo(int r) {
    return (r < 45) ? (A_LO1 + r * ATT_P) : (A_LO2 + (r - 45) * ATT_P);
}

// ---------------- fused prep A: w2 + woc + wprep ----------------
__global__ void k_prep_a(const float* __restrict__ Wq, const float* __restrict__ Wk,
                         const float* __restrict__ ctxW, const float* __restrict__ bq,
                         const float* __restrict__ Wo,
                         const float* __restrict__ Wx0, const float* __restrict__ Wx1) {
    int bid = blockIdx.x;
    if (bid < 320) {
        int idx = bid * 256 + threadIdx.x;
        int i = idx / 640, col = idx % 640;
        if (i < HH) {
            float acc;
            if (col < 512) {
                int h = col >> 7, j = col & 127;
                acc = 0.f;
                #pragma unroll 8
                for (int d = 0; d < 32; d++)
                    acc += Wq[i * HH + h * 32 + d] * Wk[j * HH + h * 32 + d];
            } else {
                acc = ctxW[i * HH + (col - 512)];
            }
            g_W2[i * 640 + col] = acc;
        }
        if (idx < 512) {
            int h = idx >> 7, j = idx & 127;
            float a = 0.f;
            #pragma unroll 8
            for (int d = 0; d < 32; d++)
                a += bq[h * 32 + d] * Wk[j * HH + h * 32 + d];
            g_bqk[idx] = a;
        }
    } else if (bid < 384) {
        int idx = (bid - 320) * 256 + threadIdx.x;   // 16384
        int i = idx >> 7, c = idx & 127;
        float acc = 0.f;
        #pragma unroll 4
        for (int m = 0; m < 128; m++)
            acc += Wo[i * 128 + m] * ctxW[(128 + m) * 128 + c];
        g_WoC[i * 128 + c] = acc;
    } else {
        int idx = (bid - 384) * 256 + threadIdx.x;   // 131072
        int l = idx / (512 * 128);
        int rem = idx % (512 * 128);
        int p = rem / 128, i = rem % 128;
        const float* Wx = l ? Wx1 : Wx0;
        float v = Wx[i * 512 + (p & 3) * 128 + (p >> 2)];
        __nv_bfloat16 hi = __float2bfloat16(v);
        float lo = v - __bfloat162float(hi);
        g_WxT_hi[l][p * 128 + i] = hi;
        g_WxT_lo[l][p * 128 + i] = __float2bfloat16(lo);
    }
}

// ---------------- fused prep B: mbig + cvec ----------------
__global__ void k_prep_b(const float* __restrict__ Wv, const float* __restrict__ ctxb,
                         const float* __restrict__ bo, const float* __restrict__ bv,
                         const float* __restrict__ ctxW) {
    int bid = blockIdx.x;
    if (bid < 128) {
        int idx = bid * 256 + threadIdx.x;
        int c = idx >> 8, pr = idx & 255;
        int h = pr >> 6, j2 = pr & 63;
        float m0 = 0.f, m1 = 0.f;
        #pragma unroll 8
        for (int d = 0; d < 32; d++) {
            float wc = g_WoC[(h * 32 + d) * 128 + c];
            m0 += Wv[(2 * j2) * 128 + h * 32 + d] * wc;
            m1 += Wv[(2 * j2 + 1) * 128 + h * 32 + d] * wc;
        }
        unsigned hh_, ll_;
        split2(m0, m1, hh_, ll_);
        g_MTp_hi[idx] = hh_;
        g_MTp_lo[idx] = ll_;
    } else if (threadIdx.x < 128) {
        int c = threadIdx.x;
        float acc = ctxb[c];
        #pragma unroll 4
        for (int i = 0; i < 128; i++) acc += bo[i] * ctxW[(128 + i) * 128 + c];
        #pragma unroll 4
        for (int j = 0; j < 128; j++) acc += bv[j] * g_WoC[j * 128 + c];
        g_cvec[c] = acc;
    }
}

__global__ __launch_bounds__(640, 1)
void k_fold(const float* __restrict__ h1, const float* __restrict__ stepq) {
    __shared__ float aS[8 * HH];
    int r0 = blockIdx.x * 8;
    bool isq = (r0 >= BB * NN);
    const float* src = isq ? (stepq + (r0 - BB * NN) * HH) : (h1 + (size_t)r0 * HH);
    for (int idx = threadIdx.x; idx < 8 * HH; idx += 640) aS[idx] = src[idx];
    __syncthreads();
    int c = threadIdx.x;
    float acc[8];
    float binit = (isq && c < 512) ? g_bqk[c] : 0.f;
    #pragma unroll
    for (int k = 0; k < 8; k++) acc[k] = binit;
    #pragma unroll 4
    for (int i = 0; i < HH; i++) {
        float w = g_W2[i * 640 + c];
        #pragma unroll
        for (int k = 0; k < 8; k++) acc[k] += aS[k * HH + i] * w;
    }
    float* dst = isq ? (g_sfold + (r0 - BB * NN) * 640) : (g_hfold + (size_t)r0 * 640);
    #pragma unroll
    for (int k = 0; k < 8; k++) dst[k * 640 + c] = acc[k];
}

__global__ __launch_bounds__(512, 1)
void k_agg(const float* __restrict__ h0, const float* __restrict__ h1,
           const float* __restrict__ adj) {
    extern __shared__ float hS[];
    float* adjS = hS + NN * HH;
    int c5 = blockIdx.x / 32;
    int lb = blockIdx.x % 32;
    int l = lb >> 4, b = lb & 15;
    const float* hsrc = (l ? h1 : h0) + (size_t)b * NN * HH;
    for (int idx = threadIdx.x; idx < NN * HH; idx += 512) hS[idx] = hsrc[idx];
    for (int idx = threadIdx.x; idx < 40 * NN; idx += 512) {
        int r = idx / NN, m = idx % NN;
        int grow = (r / 10) * 50 + c5 * 10 + (r % 10);
        adjS[idx] = adj[grow * NN + m];
    }
    __syncthreads();
    int hh = threadIdx.x & 127, g = threadIdx.x >> 7;
    int n0 = g * 50 + c5 * 10;
    const float4* adjS4 = (const float4*)adjS;
    float acc[10];
    #pragma unroll
    for (int k = 0; k < 10; k++) acc[k] = 0.f;
    for (int m4 = 0; m4 < 50; m4++) {
        float4 av[10];
        #pragma unroll
        for (int k = 0; k < 10; k++) av[k] = adjS4[(g * 10 + k) * 50 + m4];
        #pragma unroll
        for (int u = 0; u < 4; u++) {
            float hv = hS[(m4 * 4 + u) * HH + hh];
            #pragma unroll
            for (int k = 0; k < 10; k++)
                acc[k] += ((const float*)&av[k])[u] * hv;
        }
    }
    #pragma unroll
    for (int k = 0; k < 10; k++)
        g_agg[l][((size_t)b * NN + n0 + k) * HH + hh] = acc[k];
}

__global__ __launch_bounds__(512, 1)
void k_aggWh(const float* __restrict__ Wh0, const float* __restrict__ bb0,
             const float* __restrict__ Wh1, const float* __restrict__ bb1) {
    extern __shared__ float aggS[];
    int ch = blockIdx.x >> 5;
    int lb = blockIdx.x & 31;
    int l = lb >> 4, b = lb & 15;
    const float* Wh   = l ? Wh1 : Wh0;
    const float* bias = l ? bb1 : bb0;
    const float* asrc = g_agg[l] + (size_t)b * NN * HH;
    for (int idx = threadIdx.x; idx < NN * HH; idx += 512) aggS[idx] = asrc[idx];
    __syncthreads();
    int c = threadIdx.x;
    int perm = (c & 127) * 4 + (c >> 7);
    float bsv = bias[c];
    const float4* a4 = (const float4*)aggS;
    float* dst = g_aggWh[l] + (size_t)b * NN * 4 * HH;
    int n0 = ch * 50;
    float acc[50];
    #pragma unroll
    for (int k = 0; k < 50; k++) acc[k] = bsv;
    for (int i4 = 0; i4 < 32; i4++) {
        float w0 = Wh[(i4 * 4 + 0) * 512 + c];
        float w1 = Wh[(i4 * 4 + 1) * 512 + c];
        float w2 = Wh[(i4 * 4 + 2) * 512 + c];
        float w3 = Wh[(i4 * 4 + 3) * 512 + c];
        #pragma unroll
        for (int k = 0; k < 50; k++) {
            float4 a = a4[(n0 + k) * 32 + i4];
            acc[k] += a.x * w0 + a.y * w1 + a.z * w2 + a.w * w3;
        }
    }
    #pragma unroll
    for (int k = 0; k < 50; k++) dst[(n0 + k) * 512 + perm] = acc[k];
}

// ---------------- attention megakernel (unchanged) ----------------
__global__ __launch_bounds__(512, 1)
void k_attn(const float* __restrict__ enc, float* __restrict__ out_attn)
{
    extern __shared__ float sm[];
    unsigned* su = (unsigned*)sm;
    float* sc = sm + A_SC;

    const int tid = threadIdx.x;
    const int b = blockIdx.x / NN, n = blockIdx.x % NN;
    const int bn = b * NN + n;
    const int w = tid >> 5, lane = tid & 31;
    const int g = lane >> 2, tg = lane & 3;

    {
        const float4* e4 = (const float4*)enc;
        for (int idx = tid; idx < SS * 32; idx += 512) {
            int s = idx >> 5, j4 = idx & 31;
            float4 v = e4[((size_t)(b * SS + s) * NN + n) * 32 + j4];
            unsigned h0, l0, h1, l1;
            split2(v.x, v.y, h0, l0);
            split2(v.z, v.w, h1, l1);
            unsigned* dh = su + A_ESJH + s * QT_P + j4 * 2;
            unsigned* dl = su + A_ESJL + s * QT_P + j4 * 2;
            dh[0] = h0; dh[1] = h1;
            dl[0] = l0; dl[1] = l1;
        }
        const float4* sf4 = (const float4*)g_sfold;
        const float4* hf4 = (const float4*)(g_hfold + (size_t)bn * 640);
        for (int idx = tid; idx < 96 * 32; idx += 512) {
            int r = idx >> 5, j4 = idx & 31;
            int t = r >> 2;
            float4 sa = sf4[t * 160 + (r & 3) * 32 + j4];
            float4 hb = hf4[(r & 3) * 32 + j4];
            unsigned h0, l0, h1, l1;
            split2(sa.x + hb.x, sa.y + hb.y, h0, l0);
            split2(sa.z + hb.z, sa.w + hb.w, h1, l1);
            unsigned* dh = su + A_QTH + r * QT_P + j4 * 2;
            unsigned* dl = su + A_QTL + r * QT_P + j4 * 2;
            dh[0] = h0; dh[1] = h1;
            dl[0] = l0; dl[1] = l1;
        }
    }
    __syncthreads();

    {
        const float scale = 0.17677669529663687f;
        for (int job = w; job < 126; job += 16) {
            int mt = job / 21, nt = job % 21;
            float acc[4] = {0.f, 0.f, 0.f, 0.f};
            int ra = (mt * 16 + g) * QT_P;
            int rb = (nt * 8 + g) * QT_P;
            #pragma unroll
            for (int kt = 0; kt < 8; kt++) {
                int ko = kt * 8 + tg;
                unsigned a0h = su[A_QTH + ra + ko];
                unsigned a1h = su[A_QTH + ra + 8 * QT_P + ko];
                unsigned a2h = su[A_QTH + ra + ko + 4];
                unsigned a3h = su[A_QTH + ra + 8 * QT_P + ko + 4];
                unsigned a0l = su[A_QTL + ra + ko];
                unsigned a1l = su[A_QTL + ra + 8 * QT_P + ko];
                unsigned a2l = su[A_QTL + ra + ko + 4];
                unsigned a3l = su[A_QTL + ra + 8 * QT_P + ko + 4];
                unsigned b0h = su[A_ESJH + rb + ko];
                unsigned b1h = su[A_ESJH + rb + ko + 4];
                unsigned b0l = su[A_ESJL + rb + ko];
                unsigned b1l = su[A_ESJL + rb + ko + 4];
                mma16816(acc, a0h, a1h, a2h, a3h, b0h, b1h);
                mma16816(acc, a0h, a1h, a2h, a3h, b0l, b1l);
                mma16816(acc, a0l, a1l, a2l, a3l, b0h, b1h);
            }
            int row = mt * 16 + g, col = nt * 8 + 2 * tg;
            *(float2*)&sc[row * SC_P + col]       = make_float2(acc[0] * scale, acc[1] * scale);
            *(float2*)&sc[(row + 8) * SC_P + col] = make_float2(acc[2] * scale, acc[3] * scale);
        }
    }
    __syncthreads();

    {
        const float* eb = enc + ((size_t)b * SS * NN + n) * HH;
        for (int idx = tid; idx < 128 * EJ_P; idx += 512) {
            int j = idx & 127, sp = idx >> 7;
            unsigned h, l;
            if (sp < 84) {
                float v0 = eb[(size_t)(2 * sp) * NN * HH + j];
                float v1 = eb[(size_t)(2 * sp + 1) * NN * HH + j];
                split2(v0, v1, h, l);
            } else { h = 0u; l = 0u; }
            su[A_EJSH + j * EJ_P + sp] = h;
            su[A_EJSL + j * EJ_P + sp] = l;
        }
    }

    for (int k6 = 0; k6 < 6; k6++) {
        int r = k6 * 16 + w;
        float v[6];
        float mx = -1e30f;
        #pragma unroll
        for (int u = 0; u < 6; u++) {
            int s = lane + 32 * u;
            v[u] = (s < SS) ? sc[r * SC_P + s] : -1e30f;
            mx = fmaxf(mx, v[u]);
        }
        #pragma unroll
        for (int off = 16; off > 0; off >>= 1)
            mx = fmaxf(mx, __shfl_xor_sync(0xffffffffu, mx, off));
        float sum = 0.f;
        #pragma unroll
        for (int u = 0; u < 6; u++) {
            int s = lane + 32 * u;
            if (s < SS) { v[u] = __expf(v[u] - mx); sum += v[u]; }
        }
        #pragma unroll
        for (int off = 16; off > 0; off >>= 1)
            sum += __shfl_xor_sync(0xffffffffu, sum, off);
        float inv = __fdividef(1.f, sum);
        int t = r >> 2, h = r & 3;
        float* gout = out_attn + ((((size_t)b * TT + t) * NHH + h) * NN + n) * SS;
        #pragma unroll
        for (int u = 0; u < 6; u++) {
            int s = lane + 32 * u;
            if (s < SS) { v[u] *= inv; gout[s] = v[u]; }
            else v[u] = 0.f;
        }
        int lobase = attlo(r);
        #pragma unroll
        for (int u = 0; u < 6; u++) {
            float av = v[u];
            float bnx = __shfl_down_sync(0xffffffffu, av, 1);
            int s = lane + 32 * u;
            if (!(lane & 1)) {
                int p = s >> 1;
                if (p < 88) {
                    unsigned hh_, ll_;
                    split2(av, bnx, hh_, ll_);
                    su[r * ATT_P + p] = hh_;
                    su[lobase + p] = ll_;
                }
            }
        }
    }
    __syncthreads();

    float acc5[6][4];
    #pragma unroll
    for (int jj = 0; jj < 6; jj++)
        #pragma unroll
        for (int m = 0; m < 4; m++) acc5[jj][m] = 0.f;
    {
        int rb = (w * 8 + g) * EJ_P;
        #pragma unroll
        for (int jj = 0; jj < 6; jj++) {
            int r0 = jj * 16 + g;
            int ra = r0 * ATT_P;
            int ral0 = attlo(r0), ral1 = attlo(r0 + 8);
            #pragma unroll
            for (int kt = 0; kt < 11; kt++) {
                int ko = kt * 8 + tg;
                unsigned a0h = su[ra + ko];
                unsigned a1h = su[ra + 8 * ATT_P + ko];
                unsigned a2h = su[ra + ko + 4];
                unsigned a3h = su[ra + 8 * ATT_P + ko + 4];
                unsigned a0l = su[ral0 + ko];
                unsigned a1l = su[ral1 + ko];
                unsigned a2l = su[ral0 + ko + 4];
                unsigned a3l = su[ral1 + ko + 4];
                unsigned b0h = su[A_EJSH + rb + ko];
                unsigned b1h = su[A_EJSH + rb + ko + 4];
                unsigned b0l = su[A_EJSL + rb + ko];
                unsigned b1l = su[A_EJSL + rb + ko + 4];
                mma16816(acc5[jj], a0h, a1h, a2h, a3h, b0h, b1h);
                mma16816(acc5[jj], a0h, a1h, a2h, a3h, b0l, b1l);
                mma16816(acc5[jj], a0l, a1l, a2l, a3l, b0h, b1h);
            }
        }
    }
    __syncthreads();

    {
        int j2 = w * 4 + tg;
        #pragma unroll
        for (int jj = 0; jj < 6; jj++) {
            int r0 = jj * 16 + g, r1 = r0 + 8;
            unsigned hh_, ll_;
            int p0 = (r0 & 3) * 64 + j2, t0 = r0 >> 2;
            split2(acc5[jj][0], acc5[jj][1], hh_, ll_);
            su[A_APH + t0 * AP_P + p0] = hh_;
            su[A_APL + t0 * AP_P + p0] = ll_;
            int p1 = (r1 & 3) * 64 + j2, t1 = r1 >> 2;
            split2(acc5[jj][2], acc5[jj][3], hh_, ll_);
            su[A_APH + t1 * AP_P + p1] = hh_;
            su[A_APL + t1 * AP_P + p1] = ll_;
        }
        for (int i = tid; i < 8 * 256; i += 512) {
            int rr = 24 + (i >> 8), p = i & 255;
            su[A_APH + rr * AP_P + p] = 0u;
            su[A_APL + rr * AP_P + p] = 0u;
        }
    }

    float acc6[2][4];
    #pragma unroll
    for (int mt = 0; mt < 2; mt++)
        #pragma unroll
        for (int m = 0; m < 4; m++) acc6[mt][m] = 0.f;

    for (int ck = 0; ck < 8; ck++) {
        __syncthreads();
        for (int i = tid; i < 4096; i += 512) {
            int c = i >> 5, pr = i & 31;
            su[A_SC + c * BS_P + pr]        = g_MTp_hi[c * 256 + ck * 32 + pr];
            su[A_SC + 4608 + c * BS_P + pr] = g_MTp_lo[c * 256 + ck * 32 + pr];
        }
        __syncthreads();
        int rb = (w * 8 + g) * BS_P;
        #pragma unroll
        for (int mt = 0; mt < 2; mt++) {
            int ra = (mt * 16 + g) * AP_P + ck * 32;
            #pragma unroll
            for (int kt = 0; kt < 4; kt++) {
                int ko = kt * 8 + tg;
                unsigned a0h = su[A_APH + ra + ko];
                unsigned a1h = su[A_APH + ra + 8 * AP_P + ko];
                unsigned a2h = su[A_APH + ra + ko + 4];
                unsigned a3h = su[A_APH + ra + 8 * AP_P + ko + 4];
                unsigned a0l = su[A_APL + ra + ko];
                unsigned a1l = su[A_APL + ra + 8 * AP_P + ko];
                unsigned a2l = su[A_APL + ra + ko + 4];
                unsigned a3l = su[A_APL + ra + 8 * AP_P + ko + 4];
                unsigned b0h = su[A_SC + rb + ko];
                unsigned b1h = su[A_SC + rb + ko + 4];
                unsigned b0l = su[A_SC + 4608 + rb + ko];
                unsigned b1l = su[A_SC + 4608 + rb + ko + 4];
                mma16816(acc6[mt], a0h, a1h, a2h, a3h, b0h, b1h);
                mma16816(acc6[mt], a0h, a1h, a2h, a3h, b0l, b1l);
                mma16816(acc6[mt], a0l, a1l, a2l, a3l, b0h, b1h);
            }
        }
    }
    {
        int c0 = w * 8 + 2 * tg;
        float2 cv = *(const float2*)&g_cvec[c0];
        float2 hf = *(const float2*)&g_hfold[(size_t)bn * 640 + 512 + c0];
        #pragma unroll
        for (int mt = 0; mt < 2; mt++) {
            int t0 = mt * 16 + g;
            float2 sf0 = *(const float2*)&g_sfold[t0 * 640 + 512 + c0];
            *(float2*)&g_comb[((size_t)bn * TT + t0) * HH + c0] =
                make_float2(acc6[mt][0] + cv.x + hf.x + sf0.x,
                            acc6[mt][1] + cv.y + hf.y + sf0.y);
            int t1 = t0 + 8;
            if (t1 < TT) {
                float2 sf1 = *(const float2*)&g_sfold[t1 * 640 + 512 + c0];
                *(float2*)&g_comb[((size_t)bn * TT + t1) * HH + c0] =
                    make_float2(acc6[mt][2] + cv.x + hf.x + sf1.x,
                                acc6[mt][3] + cv.y + hf.y + sf1.y);
            }
        }
    }
}

// ---------------- fully fused: LN0 + gates0 + cell0 + LN1 + gates1 + cell1 + preds ----------------
__global__ __launch_bounds__(256, 2)
void k_gatesf(const float* __restrict__ c0g, const float* __restrict__ c1g,
              const float* __restrict__ lg0, const float* __restrict__ lb0,
              const float* __restrict__ lg1, const float* __restrict__ lb1,
              const float* __restrict__ outW, const float* __restrict__ outb,
              float* __restrict__ out_pred) {
    extern __shared__ unsigned su[];
    unsigned* Ah = su + G_AH;
    unsigned* Al = su + G_AL;
    unsigned* Bh = su + G_BH;
    unsigned* Bl = su + G_BL;
    float* stat = (float*)(su + G_DS);
    float* ssum = stat;          // [256] fixed-slot partial sums
    float* ssq  = stat + 256;    // [256]
    float* pP   = stat + 512;    // [256] pred partials

    const int tid = threadIdx.x;
    const int row0 = blockIdx.x * 64;
    const int w = tid >> 5, lane = tid & 31;
    const int g = lane >> 2, tg = lane & 3;
    const int mt = w >> 1, nh = w & 1;
    const int qpar = tg & 1;
    const int owner = nh * 2 + (tg >> 1);
    const int myrow = mt * 16 + g + 8 * qpar;
    const int bn = (row0 + myrow) / TT;

    // ---- LN(comb) -> Ah/Al ----
    {
        float4 gg = ((const float4*)lg0)[lane];
        float4 bbv = ((const float4*)lb0)[lane];
        for (int it = 0; it < 8; it++) {
            int r = w + it * 8;
            float4 x = ((const float4*)(g_comb + (size_t)(row0 + r) * HH))[lane];
            float s1 = x.x + x.y + x.z + x.w;
            #pragma unroll
            for (int off = 16; off > 0; off >>= 1) s1 += __shfl_xor_sync(0xffffffffu, s1, off);
            float mean = s1 * (1.f / HH);
            float dx = x.x - mean, dy = x.y - mean, dz = x.z - mean, dw = x.w - mean;
            float s2 = dx * dx + dy * dy + dz * dz + dw * dw;
            #pragma unroll
            for (int off = 16; off > 0; off >>= 1) s2 += __shfl_xor_sync(0xffffffffu, s2, off);
            float inv = rsqrtf(s2 * (1.f / HH) + 1e-5f);
            float y0 = dx * inv * gg.x + bbv.x;
            float y1 = dy * inv * gg.y + bbv.y;
            float y2 = dz * inv * gg.z + bbv.z;
            float y3 = dw * inv * gg.w + bbv.w;
            unsigned h0, l0, h1, l1;
            split2(y0, y1, h0, l0);
            split2(y2, y3, h1, l1);
            Ah[r * GA_PITCH + lane * 2]     = h0;
            Ah[r * GA_PITCH + lane * 2 + 1] = h1;
            Al[r * GA_PITCH + lane * 2]     = l0;
            Al[r * GA_PITCH + lane * 2 + 1] = l1;
        }
    }

    float hvreg[32];
    float predacc = 0.f;

    // ---- layer 0 mainloop (hv -> registers) ----
    {
        const uint4* WH = (const uint4*)g_WxT_hi[0];
        const uint4* WL = (const uint4*)g_WxT_lo[0];
        for (int nc = 0; nc < 4; nc++) {
            __syncthreads();
            for (int i = tid; i < 128 * 16; i += 256) {
                int r = i >> 4, m = i & 15;
                *(uint4*)(Bh + r * GA_PITCH + m * 4) = WH[(nc * 128 + r) * 16 + m];
                *(uint4*)(Bl + r * GA_PITCH + m * 4) = WL[(nc * 128 + r) * 16 + m];
            }
            __syncthreads();

            float acc[8][4];
            #pragma unroll
            for (int q = 0; q < 8; q++)
                #pragma unroll
                for (int m = 0; m < 4; m++) acc[q][m] = 0.f;

            const int arow = mt * 16 + g;
            #pragma unroll
            for (int kt = 0; kt < 8; kt++) {
                const int ko = kt * 8 + tg;
                unsigned a0h = Ah[arow * GA_PITCH + ko];
                unsigned a1h = Ah[(arow + 8) * GA_PITCH + ko];
                unsigned a2h = Ah[arow * GA_PITCH + ko + 4];
                unsigned a3h = Ah[(arow + 8) * GA_PITCH + ko + 4];
                unsigned a0l = Al[arow * GA_PITCH + ko];
                unsigned a1l = Al[(arow + 8) * GA_PITCH + ko];
                unsigned a2l = Al[arow * GA_PITCH + ko + 4];
                unsigned a3l = Al[(arow + 8) * GA_PITCH + ko + 4];
                #pragma unroll
                for (int q = 0; q < 8; q++) {
                    const int nrow = (nh * 8 + q) * 8 + g;
                    unsigned b0h = Bh[nrow * GA_PITCH + ko];
                    unsigned b1h = Bh[nrow * GA_PITCH + ko + 4];
                    unsigned b0l = Bl[nrow * GA_PITCH + ko];
                    unsigned b1l = Bl[nrow * GA_PITCH + ko + 4];
                    mma16816(acc[q], a0h, a1h, a2h, a3h, b0h, b1h);
                    mma16816(acc[q], a0h, a1h, a2h, a3h, b0l, b1l);
                    mma16816(acc[q], a0l, a1l, a2l, a3l, b0h, b1h);
                }
            }

            #pragma unroll
            for (int q = 0; q < 8; q++) {
                float c0 = acc[q][0], c1 = acc[q][1], c2 = acc[q][2], c3 = acc[q][3];
                float r0 = __shfl_xor_sync(0xffffffffu, c0, 1);
                float r1 = __shfl_xor_sync(0xffffffffu, c1, 1);
                float r2 = __shfl_xor_sync(0xffffffffu, c2, 1);
                float r3 = __shfl_xor_sync(0xffffffffu, c3, 1);
                float gi = qpar ? r2 : c0;
                float gf = qpar ? r3 : c1;
                float gv = qpar ? c2 : r0;
                float go = qpar ? c3 : r1;
                int hh = nc * 32 + (nh * 8 + q) * 2 + (tg >> 1);
                const float4 ag = *(const float4*)(g_aggWh[0] + (size_t)bn * 512 + hh * 4);
                gi += ag.x; gf += ag.y; gv += ag.z; go += ag.w;
                float cv = c0g[(size_t)bn * HH + hh];
                float cn = sigf(gf) * cv + sigf(gi) * tanhfast(gv);
                hvreg[nc * 8 + q] = sigf(go) * tanhfast(cn);
            }
        }
    }

    // ---- row stats (fixed-slot, deterministic) ----
    {
        float s1 = 0.f, s2 = 0.f;
        #pragma unroll
        for (int k = 0; k < 32; k++) { float v = hvreg[k]; s1 += v; s2 += v * v; }
        ssum[myrow * 4 + owner] = s1;
        ssq[myrow * 4 + owner]  = s2;
    }
    __syncthreads();   // covers layer-0 mma reads of Ah/Al as well
    float mean1, inv1;
    {
        float s1 = ssum[myrow * 4] + ssum[myrow * 4 + 1] + ssum[myrow * 4 + 2] + ssum[myrow * 4 + 3];
        float s2 = ssq[myrow * 4]  + ssq[myrow * 4 + 1]  + ssq[myrow * 4 + 2]  + ssq[myrow * 4 + 3];
        mean1 = s1 * (1.f / HH);
        float var = fmaxf(s2 * (1.f / HH) - mean1 * mean1, 0.f);
        inv1 = rsqrtf(var + 1e-5f);
    }

    // ---- LN1 in-register -> Ah/Al; fold residual into preds ----
    #pragma unroll
    for (int k = 0; k < 32; k++) {
        int nc = k >> 3, q = k & 7;
        int hh = nc * 32 + (nh * 8 + q) * 2 + (tg >> 1);
        float x1v = hvreg[k];
        predacc += x1v * __ldg(&outW[hh]);
        float y = (x1v - mean1) * inv1 * __ldg(&lg1[hh]) + __ldg(&lb1[hh]);
        float yo = __shfl_xor_sync(0xffffffffu, y, 2);
        if ((tg >> 1) == 0) {
            int z = nc * 16 + nh * 8 + q;
            unsigned hb, lbv;
            split2(y, yo, hb, lbv);
            Ah[myrow * GA_PITCH + z] = hb;
            Al[myrow * GA_PITCH + z] = lbv;
        }
    }

    // ---- layer 1 mainloop ----
    {
        const uint4* WH = (const uint4*)g_WxT_hi[1];
        const uint4* WL = (const uint4*)g_WxT_lo[1];
        for (int nc = 0; nc < 4; nc++) {
            __syncthreads();
            for (int i = tid; i < 128 * 16; i += 256) {
                int r = i >> 4, m = i & 15;
                *(uint4*)(Bh + r * GA_PITCH + m * 4) = WH[(nc * 128 + r) * 16 + m];
                *(uint4*)(Bl + r * GA_PITCH + m * 4) = WL[(nc * 128 + r) * 16 + m];
            }
            __syncthreads();

            float acc[8][4];
            #pragma unroll
            for (int q = 0; q < 8; q++)
                #pragma unroll
                for (int m = 0; m < 4; m++) acc[q][m] = 0.f;

            const int arow = mt * 16 + g;
            #pragma unroll
            for (int kt = 0; kt < 8; kt++) {
                const int ko = kt * 8 + tg;
                unsigned a0h = Ah[arow * GA_PITCH + ko];
                unsigned a1h = Ah[(arow + 8) * GA_PITCH + ko];
                unsigned a2h = Ah[arow * GA_PITCH + ko + 4];
                unsigned a3h = Ah[(arow + 8) * GA_PITCH + ko + 4];
                unsigned a0l = Al[arow * GA_PITCH + ko];
                unsigned a1l = Al[(arow + 8) * GA_PITCH + ko];
                unsigned a2l = Al[arow * GA_PITCH + ko + 4];
                unsigned a3l = Al[(arow + 8) * GA_PITCH + ko + 4];
                #pragma unroll
                for (int q = 0; q < 8; q++) {
                    const int nrow = (nh * 8 + q) * 8 + g;
                    unsigned b0h = Bh[nrow * GA_PITCH + ko];
                    unsigned b1h = Bh[nrow * GA_PITCH + ko + 4];
                    unsigned b0l = Bl[nrow * GA_PITCH + ko];
                    unsigned b1l = Bl[nrow * GA_PITCH + ko + 4];
                    mma16816(acc[q], a0h, a1h, a2h, a3h, b0h, b1h);
                    mma16816(acc[q], a0h, a1h, a2h, a3h, b0l, b1l);
                    mma16816(acc[q], a0l, a1l, a2l, a3l, b0h, b1h);
                }
            }

            #pragma unroll
            for (int q = 0; q < 8; q++) {
                float c0 = acc[q][0], c1 = acc[q][1], c2 = acc[q][2], c3 = acc[q][3];
                float r0 = __shfl_xor_sync(0xffffffffu, c0, 1);
                float r1 = __shfl_xor_sync(0xffffffffu, c1, 1);
                float r2 = __shfl_xor_sync(0xffffffffu, c2, 1);
                float r3 = __shfl_xor_sync(0xffffffffu, c3, 1);
                float gi = qpar ? r2 : c0;
                float gf = qpar ? r3 : c1;
                float gv = qpar ? c2 : r0;
                float go = qpar ? c3 : r1;
                int hh = nc * 32 + (nh * 8 + q) * 2 + (tg >> 1);
                const float4 ag = *(const float4*)(g_aggWh[1] + (size_t)bn * 512 + hh * 4);
                gi += ag.x; gf += ag.y; gv += ag.z; go += ag.w;
                float cv = c1g[(size_t)bn * HH + hh];
                float cn = sigf(gf) * cv + sigf(gi) * tanhfast(gv);
                float hv = sigf(go) * tanhfast(cn);
                predacc += hv * __ldg(&outW[hh]);
            }
        }
    }

    // ---- preds: fixed-slot reduce, deterministic ----
    pP[myrow * 4 + owner] = predacc;
    __syncthreads();
    if (tid < 64) {
        float p = pP[tid * 4] + pP[tid * 4 + 1] + pP[tid * 4 + 2] + pP[tid * 4 + 3];
        int grow = row0 + tid;
        int bnn = grow / TT, t = grow % TT;
        int bI = bnn / NN, nI = bnn % NN;
        out_pred[((size_t)bI * TT + t) * NN + nI] = p + outb[0];
    }
}

extern "C" void kernel_launch(void* const* d_in, const int* in_sizes, int n_in,
                              void* d_out, int out_size) {
    const float* enc   = (const float*)d_in[0];
    const float* h0    = (const float*)d_in[1];
    const float* c0    = (const float*)d_in[2];
    const float* h1    = (const float*)d_in[3];
    const float* c1    = (const float*)d_in[4];
    const float* adj   = (const float*)d_in[5];
    const float* stepq = (const float*)d_in[6];
    const float* Wq    = (const float*)d_in[7];
    const float* bq    = (const float*)d_in[8];
    const float* Wk    = (const float*)d_in[9];
    // d_in[10] = bk: softmax-invariant, unused
    const float* Wv    = (const float*)d_in[11];
    const float* bv    = (const float*)d_in[12];
    const float* Wo    = (const float*)d_in[13];
    const float* bo    = (const float*)d_in[14];
    const float* ctxW  = (const float*)d_in[15];
    const float* ctxb  = (const float*)d_in[16];
    const float* Wx0   = (const float*)d_in[17];
    const float* Wh0   = (const float*)d_in[18];
    const float* b0    = (const float*)d_in[19];
    const float* lng0  = (const float*)d_in[20];
    const float* lnb0  = (const float*)d_in[21];
    const float* Wx1   = (const float*)d_in[22];
    const float* Wh1   = (const float*)d_in[23];
    const float* b1    = (const float*)d_in[24];
    const float* lng1  = (const float*)d_in[25];
    const float* lnb1  = (const float*)d_in[26];
    const float* outW  = (const float*)d_in[27];
    const float* outb  = (const float*)d_in[28];

    float* out      = (float*)d_out;
    float* out_pred = out;
    float* out_attn = out + (size_t)BB * TT * NN;

    cudaFuncSetAttribute(k_attn, cudaFuncAttributeMaxDynamicSharedMemorySize, ATTN_SMEM_BYTES);
    cudaFuncSetAttribute(k_agg, cudaFuncAttributeMaxDynamicSharedMemorySize, AGG_SMEM);
    cudaFuncSetAttribute(k_aggWh, cudaFuncAttributeMaxDynamicSharedMemorySize, NN * HH * 4);
    cudaFuncSetAttribute(k_gatesf, cudaFuncAttributeMaxDynamicSharedMemorySize, G_SMEM_BYTES);

    k_prep_a<<<896, 256>>>(Wq, Wk, ctxW, bq, Wo, Wx0, Wx1);
    k_prep_b<<<129, 256>>>(Wv, ctxb, bo, bv, ctxW);
    k_fold<<<(BB * NN + TT) / 8, 640>>>(h1, stepq);
    k_attn<<<BB * NN, 512, ATTN_SMEM_BYTES>>>(enc, out_attn);   // launch idx 3 -> profiled
    k_agg<<<5 * 2 * BB, 512, AGG_SMEM>>>(h0, h1, adj);
    k_aggWh<<<4 * 2 * BB, 512, NN * HH * 4>>>(Wh0, b0, Wh1, b1);
    k_gatesf<<<NROWS / 64, 256, G_SMEM_BYTES>>>(c0, c1, lng0, lnb0, lng1, lnb1,
                                                outW, outb, out_pred);
}